// round 2
// baseline (speedup 1.0000x reference)
#include <cuda_runtime.h>
#include <cstdint>

#define N_NODES 100000
#define N_EDGES 1600000
#define IN_CH   128
#define HID     64
#define NG      256
#define OUTC    10

typedef unsigned long long u64;

// ---------------- scratch (device globals; no allocation) ----------------
__device__ int   g_is64;
__device__ int   g_deg[N_NODES];          // edge count per dst (no self loop)
__device__ int   g_rowstart[N_NODES];
__device__ int   g_cursor[N_NODES];
__device__ int   g_esrc[N_EDGES];         // CSR: src node per edge, bucketed by dst
__device__ float g_dinv[N_NODES];
__device__ float g_hs [(size_t)N_NODES * HID];   // (x@W)*dinv[node]
__device__ float g_pool[NG * HID];
__device__ float g_cnt [NG];

// index loader handling int64-vs-int32 edge/batch buffers
__device__ __forceinline__ int load_idx(const void* p, long long i, int is64) {
    if (is64) return (int)((const long long*)p)[i];
    return ((const int*)p)[i];
}

__device__ __forceinline__ void fma2(u64& d, u64 a, u64 b) {
    asm("fma.rn.f32x2 %0, %1, %2, %0;" : "+l"(d) : "l"(a), "l"(b));
}
__device__ __forceinline__ u64 pack2(float v) {
    u64 r; asm("mov.b64 %0, {%1, %1};" : "=l"(r) : "f"(v)); return r;
}
__device__ __forceinline__ void unpack2(u64 v, float& lo, float& hi) {
    asm("mov.b64 {%0, %1}, %2;" : "=f"(lo), "=f"(hi) : "l"(v));
}

// ---------------- dtype sniff: int64 => odd 32-bit words are 0 ----------------
__global__ void k_detect(const unsigned* __restrict__ e) {
    if (blockIdx.x == 0 && threadIdx.x == 0) {
        int z = 1;
        for (int i = 0; i < 64; i++) {
            if (e[2 * i + 1] != 0u) { z = 0; break; }
        }
        g_is64 = z;
    }
}

// ---------------- init: zero counters ----------------
__global__ void k_init() {
    int i = blockIdx.x * blockDim.x + threadIdx.x;
    if (i < N_NODES) g_deg[i] = 0;
    if (i < NG * HID) g_pool[i] = 0.f;
    if (i < NG) g_cnt[i] = 0.f;
}

// ---------------- in-degree count over dst (edges only) ----------------
__global__ void k_degcount(const void* __restrict__ ei) {
    int i = blockIdx.x * blockDim.x + threadIdx.x;
    if (i < N_EDGES) {
        int d = load_idx(ei, (long long)N_EDGES + i, g_is64);
        atomicAdd(&g_deg[d], 1);
    }
}

// ---------------- single-block exclusive scan + dinv ----------------
__global__ __launch_bounds__(1024) void k_scan() {
    const int t = threadIdx.x;
    const int PER = 98;                         // 1024*98 >= 100000
    int base = t * PER;
    int end = base + PER; if (end > N_NODES) end = N_NODES;
    int s = 0;
    for (int i = base; i < end; i++) s += g_deg[i];

    __shared__ int wsum[32];
    const int lane = t & 31, wid = t >> 5;
    int v = s;
#pragma unroll
    for (int o = 1; o < 32; o <<= 1) {
        int u = __shfl_up_sync(0xffffffffu, v, o);
        if (lane >= o) v += u;
    }
    if (lane == 31) wsum[wid] = v;
    __syncthreads();
    if (wid == 0) {
        int w = wsum[lane];
#pragma unroll
        for (int o = 1; o < 32; o <<= 1) {
            int u = __shfl_up_sync(0xffffffffu, w, o);
            if (lane >= o) w += u;
        }
        wsum[lane] = w;
    }
    __syncthreads();
    int run = (v - s) + (wid ? wsum[wid - 1] : 0);  // exclusive prefix for this thread
    for (int i = base; i < end; i++) {
        int d = g_deg[i];
        g_rowstart[i] = run;
        g_cursor[i]   = run;
        g_dinv[i]     = rsqrtf((float)(d + 1));    // +1 self loop
        run += d;
    }
}

// ---------------- CSR fill: bucket src by dst ----------------
__global__ void k_fill(const void* __restrict__ ei) {
    int i = blockIdx.x * blockDim.x + threadIdx.x;
    if (i < N_EDGES) {
        const int is64 = g_is64;
        int s = load_idx(ei, i, is64);
        int d = load_idx(ei, (long long)N_EDGES + i, is64);
        int pos = atomicAdd(&g_cursor[d], 1);
        g_esrc[pos] = s;
    }
}

// ---------------- GEMM: hs = (x @ W) * dinv, packed f32x2 FMA -----------------
// block tile: 128 rows x 64 cols; thread: 4 rows (stride 32) x 8 cols.
// K=128 in 4 phases of 32. 256 threads: ty=t>>3 (0..31), tx=t&7.
__global__ __launch_bounds__(256) void k_gemm(const float* __restrict__ x,
                                              const float* __restrict__ W) {
    __shared__ __align__(16) float Ws[32 * 64];       // [k][c]  8KB
    __shared__ __align__(16) float Xs[128 * 36];      // [row][k] stride 36, 18KB

    const int t    = threadIdx.x;
    const int ty   = t >> 3;            // 0..31
    const int tx   = t & 7;             // 0..7
    const int row0 = blockIdx.x * 128;

    u64 acc[4][4];
#pragma unroll
    for (int r = 0; r < 4; r++)
#pragma unroll
        for (int j = 0; j < 4; j++) acc[r][j] = 0ull;

    for (int ph = 0; ph < 4; ph++) {
        __syncthreads();
        // W slab: 32x64 floats = 512 float4, 2 per thread
#pragma unroll
        for (int i = t; i < 512; i += 256) {
            ((float4*)Ws)[i] = ((const float4*)(W + ph * 32 * 64))[i];
        }
        // X tile: 128 rows x 32 cols = 1024 float4, 4 per thread
#pragma unroll
        for (int i = t; i < 1024; i += 256) {
            int rr = i >> 3, c4 = i & 7;
            int gr = row0 + rr;
            if (gr >= N_NODES) gr = N_NODES - 1;
            float4 v = ((const float4*)(x + (size_t)gr * IN_CH + ph * 32))[c4];
            *(float4*)(Xs + rr * 36 + c4 * 4) = v;
        }
        __syncthreads();

#pragma unroll
        for (int k = 0; k < 32; k++) {
            u64 xx[4];
#pragma unroll
            for (int r = 0; r < 4; r++)
                xx[r] = pack2(Xs[(ty + 32 * r) * 36 + k]);
            ulonglong2 wA = *(const ulonglong2*)(Ws + k * 64 + tx * 8);
            ulonglong2 wB = *(const ulonglong2*)(Ws + k * 64 + tx * 8 + 4);
#pragma unroll
            for (int r = 0; r < 4; r++) {
                fma2(acc[r][0], xx[r], wA.x);
                fma2(acc[r][1], xx[r], wA.y);
                fma2(acc[r][2], xx[r], wB.x);
                fma2(acc[r][3], xx[r], wB.y);
            }
        }
    }

#pragma unroll
    for (int r = 0; r < 4; r++) {
        int row = row0 + ty + 32 * r;
        if (row < N_NODES) {
            float dv = g_dinv[row];
            float o[8];
#pragma unroll
            for (int j = 0; j < 4; j++) unpack2(acc[r][j], o[2 * j], o[2 * j + 1]);
            float4 o0 = make_float4(o[0] * dv, o[1] * dv, o[2] * dv, o[3] * dv);
            float4 o1 = make_float4(o[4] * dv, o[5] * dv, o[6] * dv, o[7] * dv);
            float4* hp = (float4*)(g_hs + (size_t)row * HID + tx * 8);
            hp[0] = o0; hp[1] = o1;
        }
    }
}

// ---------------- aggregate + relu + pool: warp per node, lane owns float2 ----
__global__ __launch_bounds__(256) void k_agg(const void* __restrict__ batch,
                                             const float* __restrict__ bconv) {
    const int gt   = blockIdx.x * blockDim.x + threadIdx.x;
    const int node = gt >> 5;
    const int lane = gt & 31;
    const int c    = lane * 2;

    // self-loop term
    float2 sum = *(const float2*)(g_hs + (size_t)node * HID + c);

    const int rs = g_rowstart[node];
    const int d  = g_deg[node];
    const int* ep = g_esrc + rs;

    int e = 0;
    for (; e + 4 <= d; e += 4) {
        int s0 = __ldg(ep + e + 0);
        int s1 = __ldg(ep + e + 1);
        int s2 = __ldg(ep + e + 2);
        int s3 = __ldg(ep + e + 3);
        float2 v0 = *(const float2*)(g_hs + (size_t)s0 * HID + c);
        float2 v1 = *(const float2*)(g_hs + (size_t)s1 * HID + c);
        float2 v2 = *(const float2*)(g_hs + (size_t)s2 * HID + c);
        float2 v3 = *(const float2*)(g_hs + (size_t)s3 * HID + c);
        sum.x += (v0.x + v1.x) + (v2.x + v3.x);
        sum.y += (v0.y + v1.y) + (v2.y + v3.y);
    }
    for (; e < d; e++) {
        int s0 = __ldg(ep + e);
        float2 v0 = *(const float2*)(g_hs + (size_t)s0 * HID + c);
        sum.x += v0.x; sum.y += v0.y;
    }

    const float dv = g_dinv[node];
    float2 b = ((const float2*)bconv)[lane];
    float hx = fmaxf(fmaf(dv, sum.x, b.x), 0.f);
    float hy = fmaxf(fmaf(dv, sum.y, b.y), 0.f);

    const int g = load_idx(batch, node, g_is64);
    float* pp = g_pool + g * HID + c;
    asm volatile("red.global.add.v2.f32 [%0], {%1, %2};"
                 :: "l"(pp), "f"(hx), "f"(hy) : "memory");
    if (lane == 0) atomicAdd(&g_cnt[g], 1.0f);
}

// ---------------- final: out = (pool/cnt) @ W_lin + b_lin ----------------
__global__ __launch_bounds__(256) void k_final(const float* __restrict__ Wl,
                                               const float* __restrict__ bl,
                                               float* __restrict__ out) {
    __shared__ float sW[HID * OUTC];
    __shared__ float sb[OUTC];
    const int t = threadIdx.x;
    for (int i = t; i < HID * OUTC; i += 256) sW[i] = Wl[i];
    if (t < OUTC) sb[t] = bl[t];
    __syncthreads();

    const float inv = 1.f / fmaxf(g_cnt[t], 1.f);
    float acc[OUTC];
#pragma unroll
    for (int j = 0; j < OUTC; j++) acc[j] = sb[j];
#pragma unroll 4
    for (int c = 0; c < HID; c++) {
        float p = g_pool[t * HID + c] * inv;
#pragma unroll
        for (int j = 0; j < OUTC; j++) acc[j] = fmaf(p, sW[c * OUTC + j], acc[j]);
    }
#pragma unroll
    for (int j = 0; j < OUTC; j++) out[t * OUTC + j] = acc[j];
}

// ---------------- launch ----------------
extern "C" void kernel_launch(void* const* d_in, const int* in_sizes, int n_in,
                              void* d_out, int out_size) {
    const float* x     = (const float*)d_in[0];
    const void*  ei    = d_in[1];
    const void*  batch = d_in[2];
    const float* Wc    = (const float*)d_in[3];
    const float* bc    = (const float*)d_in[4];
    const float* Wl    = (const float*)d_in[5];
    const float* bl    = (const float*)d_in[6];
    float*       out   = (float*)d_out;

    k_detect  <<<1, 32>>>((const unsigned*)ei);
    k_init    <<<(N_NODES + 255) / 256, 256>>>();
    k_degcount<<<(N_EDGES + 255) / 256, 256>>>(ei);
    k_scan    <<<1, 1024>>>();
    k_fill    <<<(N_EDGES + 255) / 256, 256>>>(ei);
    k_gemm    <<<(N_NODES + 127) / 128, 256>>>(x, Wc);
    k_agg     <<<(N_NODES * 32) / 256, 256>>>(batch, bc);
    k_final   <<<1, 256>>>(Wl, bl, out);
}

// round 3
// speedup vs baseline: 1.9534x; 1.9534x over previous
#include <cuda_runtime.h>
#include <cstdint>

#define N_NODES 100000
#define N_EDGES 1600000
#define IN_CH   128
#define HID     64
#define NG      256
#define OUTC    10

#define SCAN_B  1024
#define SCAN_NB ((N_NODES + SCAN_B - 1) / SCAN_B)   // 98

typedef unsigned long long u64;

// ---------------- scratch (device globals; no allocation) ----------------
__device__ int   g_is64;
__device__ int   g_deg[N_NODES];          // edge count per dst (no self loop)
__device__ int   g_rowstart[N_NODES];
__device__ int   g_cursor[N_NODES];
__device__ int   g_esrc[N_EDGES];         // CSR: src node per edge, bucketed by dst
__device__ int   g_bsum[SCAN_NB];
__device__ int   g_boff[SCAN_NB];
__device__ float g_dinv[N_NODES];
__device__ float g_hs [(size_t)N_NODES * HID];   // (x@W)*dinv[node]
__device__ float g_pool[NG * HID];
__device__ float g_cnt [NG];

// index loader handling int64-vs-int32 edge/batch buffers
__device__ __forceinline__ int load_idx(const void* p, long long i, int is64) {
    if (is64) return (int)((const long long*)p)[i];
    return ((const int*)p)[i];
}

__device__ __forceinline__ void fma2(u64& d, u64 a, u64 b) {
    asm("fma.rn.f32x2 %0, %1, %2, %0;" : "+l"(d) : "l"(a), "l"(b));
}
__device__ __forceinline__ u64 pack2(float v) {
    u64 r; asm("mov.b64 %0, {%1, %1};" : "=l"(r) : "f"(v)); return r;
}
__device__ __forceinline__ void unpack2(u64 v, float& lo, float& hi) {
    asm("mov.b64 {%0, %1}, %2;" : "=f"(lo), "=f"(hi) : "l"(v));
}

// ---------------- dtype sniff: int64 => odd 32-bit words are 0 ----------------
__global__ void k_detect(const unsigned* __restrict__ e) {
    if (blockIdx.x == 0 && threadIdx.x == 0) {
        int z = 1;
        for (int i = 0; i < 64; i++) {
            if (e[2 * i + 1] != 0u) { z = 0; break; }
        }
        g_is64 = z;
    }
}

// ---------------- init: zero counters ----------------
__global__ void k_init() {
    int i = blockIdx.x * blockDim.x + threadIdx.x;
    if (i < N_NODES) g_deg[i] = 0;
    if (i < NG * HID) g_pool[i] = 0.f;
    if (i < NG) g_cnt[i] = 0.f;
}

// ---------------- in-degree count over dst (edges only) ----------------
__global__ void k_degcount(const void* __restrict__ ei) {
    int i = blockIdx.x * blockDim.x + threadIdx.x;
    if (i < N_EDGES) {
        int d = load_idx(ei, (long long)N_EDGES + i, g_is64);
        atomicAdd(&g_deg[d], 1);
    }
}

// ---------------- scan stage 1: per-block degree sums ----------------
__global__ __launch_bounds__(SCAN_B) void k_blocksum() {
    __shared__ int ws[32];
    const int t = threadIdx.x;
    const int i = blockIdx.x * SCAN_B + t;
    int v = (i < N_NODES) ? g_deg[i] : 0;
#pragma unroll
    for (int o = 16; o > 0; o >>= 1) v += __shfl_down_sync(0xffffffffu, v, o);
    if ((t & 31) == 0) ws[t >> 5] = v;
    __syncthreads();
    if (t < 32) {
        int s = ws[t];
#pragma unroll
        for (int o = 16; o > 0; o >>= 1) s += __shfl_down_sync(0xffffffffu, s, o);
        if (t == 0) g_bsum[blockIdx.x] = s;
    }
}

// ---------------- scan stage 2: exclusive scan of 98 block sums ----------------
__global__ __launch_bounds__(128) void k_scanb() {
    __shared__ int sh[128];
    const int t = threadIdx.x;
    sh[t] = (t < SCAN_NB) ? g_bsum[t] : 0;
    __syncthreads();
    // Hillis-Steele inclusive
#pragma unroll
    for (int o = 1; o < 128; o <<= 1) {
        int v = (t >= o) ? sh[t - o] : 0;
        __syncthreads();
        sh[t] += v;
        __syncthreads();
    }
    if (t < SCAN_NB) g_boff[t] = (t == 0) ? 0 : sh[t - 1];
}

// ---------------- scan stage 3: block-local exclusive scan + emit ----------------
__global__ __launch_bounds__(SCAN_B) void k_rowstart() {
    __shared__ int ws[32];
    const int t = threadIdx.x;
    const int lane = t & 31, wid = t >> 5;
    const int i = blockIdx.x * SCAN_B + t;
    int d = (i < N_NODES) ? g_deg[i] : 0;
    int v = d;
#pragma unroll
    for (int o = 1; o < 32; o <<= 1) {
        int u = __shfl_up_sync(0xffffffffu, v, o);
        if (lane >= o) v += u;
    }
    if (lane == 31) ws[wid] = v;
    __syncthreads();
    if (t < 32) {
        int w = ws[t];
#pragma unroll
        for (int o = 1; o < 32; o <<= 1) {
            int u = __shfl_up_sync(0xffffffffu, w, o);
            if (t >= o) w += u;
        }
        ws[t] = w;
    }
    __syncthreads();
    int ex = (v - d) + (wid ? ws[wid - 1] : 0) + g_boff[blockIdx.x];
    if (i < N_NODES) {
        g_rowstart[i] = ex;
        g_cursor[i]   = ex;
        g_dinv[i]     = rsqrtf((float)(d + 1));    // +1 self loop
    }
}

// ---------------- CSR fill: bucket src by dst ----------------
__global__ void k_fill(const void* __restrict__ ei) {
    int i = blockIdx.x * blockDim.x + threadIdx.x;
    if (i < N_EDGES) {
        const int is64 = g_is64;
        int s = load_idx(ei, i, is64);
        int d = load_idx(ei, (long long)N_EDGES + i, is64);
        int pos = atomicAdd(&g_cursor[d], 1);
        g_esrc[pos] = s;
    }
}

// ---------------- GEMM: hs = (x @ W) * dinv, packed f32x2 FMA -----------------
// block tile: 128 rows x 64 cols; thread: 4 rows (stride 32) x 8 cols.
// K=128 in 4 phases of 32. 256 threads: ty=t>>3 (0..31), tx=t&7.
__global__ __launch_bounds__(256) void k_gemm(const float* __restrict__ x,
                                              const float* __restrict__ W) {
    __shared__ __align__(16) float Ws[32 * 64];       // [k][c]  8KB
    __shared__ __align__(16) float Xs[128 * 36];      // [row][k] stride 36, 18KB

    const int t    = threadIdx.x;
    const int ty   = t >> 3;            // 0..31
    const int tx   = t & 7;             // 0..7
    const int row0 = blockIdx.x * 128;

    u64 acc[4][4];
#pragma unroll
    for (int r = 0; r < 4; r++)
#pragma unroll
        for (int j = 0; j < 4; j++) acc[r][j] = 0ull;

    for (int ph = 0; ph < 4; ph++) {
        __syncthreads();
        // W slab: 32x64 floats = 512 float4, 2 per thread
#pragma unroll
        for (int i = t; i < 512; i += 256) {
            ((float4*)Ws)[i] = ((const float4*)(W + ph * 32 * 64))[i];
        }
        // X tile: 128 rows x 32 cols = 1024 float4, 4 per thread
#pragma unroll
        for (int i = t; i < 1024; i += 256) {
            int rr = i >> 3, c4 = i & 7;
            int gr = row0 + rr;
            if (gr >= N_NODES) gr = N_NODES - 1;
            float4 v = ((const float4*)(x + (size_t)gr * IN_CH + ph * 32))[c4];
            *(float4*)(Xs + rr * 36 + c4 * 4) = v;
        }
        __syncthreads();

#pragma unroll
        for (int k = 0; k < 32; k++) {
            u64 xx[4];
#pragma unroll
            for (int r = 0; r < 4; r++)
                xx[r] = pack2(Xs[(ty + 32 * r) * 36 + k]);
            ulonglong2 wA = *(const ulonglong2*)(Ws + k * 64 + tx * 8);
            ulonglong2 wB = *(const ulonglong2*)(Ws + k * 64 + tx * 8 + 4);
#pragma unroll
            for (int r = 0; r < 4; r++) {
                fma2(acc[r][0], xx[r], wA.x);
                fma2(acc[r][1], xx[r], wA.y);
                fma2(acc[r][2], xx[r], wB.x);
                fma2(acc[r][3], xx[r], wB.y);
            }
        }
    }

#pragma unroll
    for (int r = 0; r < 4; r++) {
        int row = row0 + ty + 32 * r;
        if (row < N_NODES) {
            float dv = g_dinv[row];
            float o[8];
#pragma unroll
            for (int j = 0; j < 4; j++) unpack2(acc[r][j], o[2 * j], o[2 * j + 1]);
            float4 o0 = make_float4(o[0] * dv, o[1] * dv, o[2] * dv, o[3] * dv);
            float4 o1 = make_float4(o[4] * dv, o[5] * dv, o[6] * dv, o[7] * dv);
            float4* hp = (float4*)(g_hs + (size_t)row * HID + tx * 8);
            hp[0] = o0; hp[1] = o1;
        }
    }
}

// ---------------- aggregate + relu + pool: warp per node, lane owns float2 ----
__global__ __launch_bounds__(256) void k_agg(const void* __restrict__ batch,
                                             const float* __restrict__ bconv) {
    const int gt   = blockIdx.x * blockDim.x + threadIdx.x;
    const int node = gt >> 5;
    const int lane = gt & 31;
    const int c    = lane * 2;

    // self-loop term
    float2 sum = *(const float2*)(g_hs + (size_t)node * HID + c);

    const int rs = g_rowstart[node];
    const int d  = g_deg[node];
    const int* ep = g_esrc + rs;

    int e = 0;
    for (; e + 4 <= d; e += 4) {
        int s0 = __ldg(ep + e + 0);
        int s1 = __ldg(ep + e + 1);
        int s2 = __ldg(ep + e + 2);
        int s3 = __ldg(ep + e + 3);
        float2 v0 = *(const float2*)(g_hs + (size_t)s0 * HID + c);
        float2 v1 = *(const float2*)(g_hs + (size_t)s1 * HID + c);
        float2 v2 = *(const float2*)(g_hs + (size_t)s2 * HID + c);
        float2 v3 = *(const float2*)(g_hs + (size_t)s3 * HID + c);
        sum.x += (v0.x + v1.x) + (v2.x + v3.x);
        sum.y += (v0.y + v1.y) + (v2.y + v3.y);
    }
    for (; e < d; e++) {
        int s0 = __ldg(ep + e);
        float2 v0 = *(const float2*)(g_hs + (size_t)s0 * HID + c);
        sum.x += v0.x; sum.y += v0.y;
    }

    const float dv = g_dinv[node];
    float2 b = ((const float2*)bconv)[lane];
    float hx = fmaxf(fmaf(dv, sum.x, b.x), 0.f);
    float hy = fmaxf(fmaf(dv, sum.y, b.y), 0.f);

    const int g = load_idx(batch, node, g_is64);
    float* pp = g_pool + g * HID + c;
    asm volatile("red.global.add.v2.f32 [%0], {%1, %2};"
                 :: "l"(pp), "f"(hx), "f"(hy) : "memory");
    if (lane == 0) atomicAdd(&g_cnt[g], 1.0f);
}

// ---------------- final: out = (pool/cnt) @ W_lin + b_lin ----------------
__global__ __launch_bounds__(256) void k_final(const float* __restrict__ Wl,
                                               const float* __restrict__ bl,
                                               float* __restrict__ out) {
    __shared__ float sW[HID * OUTC];
    __shared__ float sb[OUTC];
    const int t = threadIdx.x;
    for (int i = t; i < HID * OUTC; i += 256) sW[i] = Wl[i];
    if (t < OUTC) sb[t] = bl[t];
    __syncthreads();

    const float inv = 1.f / fmaxf(g_cnt[t], 1.f);
    float acc[OUTC];
#pragma unroll
    for (int j = 0; j < OUTC; j++) acc[j] = sb[j];
#pragma unroll 4
    for (int c = 0; c < HID; c++) {
        float p = g_pool[t * HID + c] * inv;
#pragma unroll
        for (int j = 0; j < OUTC; j++) acc[j] = fmaf(p, sW[c * OUTC + j], acc[j]);
    }
#pragma unroll
    for (int j = 0; j < OUTC; j++) out[t * OUTC + j] = acc[j];
}

// ---------------- launch ----------------
extern "C" void kernel_launch(void* const* d_in, const int* in_sizes, int n_in,
                              void* d_out, int out_size) {
    const float* x     = (const float*)d_in[0];
    const void*  ei    = d_in[1];
    const void*  batch = d_in[2];
    const float* Wc    = (const float*)d_in[3];
    const float* bc    = (const float*)d_in[4];
    const float* Wl    = (const float*)d_in[5];
    const float* bl    = (const float*)d_in[6];
    float*       out   = (float*)d_out;

    k_detect   <<<1, 32>>>((const unsigned*)ei);
    k_init     <<<(N_NODES + 255) / 256, 256>>>();
    k_degcount <<<(N_EDGES + 255) / 256, 256>>>(ei);
    k_blocksum <<<SCAN_NB, SCAN_B>>>();
    k_scanb    <<<1, 128>>>();
    k_rowstart <<<SCAN_NB, SCAN_B>>>();
    k_fill     <<<(N_EDGES + 255) / 256, 256>>>(ei);
    k_gemm     <<<(N_NODES + 127) / 128, 256>>>(x, Wc);
    k_agg      <<<(N_NODES * 32) / 256, 256>>>(batch, bc);
    k_final    <<<1, 256>>>(Wl, bl, out);
}

// round 5
// speedup vs baseline: 2.0365x; 1.0425x over previous
#include <cuda_runtime.h>
#include <cuda_fp16.h>
#include <cstdint>

#define N_NODES 100000
#define N_EDGES 1600000
#define IN_CH   128
#define HID     64
#define NG      256
#define OUTC    10

#define SCAN_B  1024
#define SCAN_NB ((N_NODES + SCAN_B - 1) / SCAN_B)   // 98

typedef unsigned long long u64;

// ---------------- scratch (device globals; no allocation) ----------------
__device__ int    g_is64;
__device__ int    g_deg[N_NODES];          // edge count per dst (no self loop)
__device__ int    g_rowstart[N_NODES];
__device__ int    g_cursor[N_NODES];
__device__ int    g_esrc[N_EDGES];         // CSR: src node per edge, bucketed by dst
__device__ int    g_bsum[SCAN_NB];
__device__ int    g_boff[SCAN_NB];
__device__ float  g_dinv[N_NODES];
__device__ __half g_hs [(size_t)N_NODES * HID];   // (x@W)*dinv[node], fp16 storage
__device__ float  g_pool[NG * HID];
__device__ float  g_cnt [NG];

// index loader handling int64-vs-int32 edge/batch buffers
__device__ __forceinline__ int load_idx(const void* p, long long i, int is64) {
    if (is64) return (int)((const long long*)p)[i];
    return ((const int*)p)[i];
}

__device__ __forceinline__ void fma2(u64& d, u64 a, u64 b) {
    asm("fma.rn.f32x2 %0, %1, %2, %0;" : "+l"(d) : "l"(a), "l"(b));
}
__device__ __forceinline__ u64 pack2(float v) {
    u64 r; asm("mov.b64 %0, {%1, %1};" : "=l"(r) : "f"(v)); return r;
}
__device__ __forceinline__ void unpack2(u64 v, float& lo, float& hi) {
    asm("mov.b64 {%0, %1}, %2;" : "=f"(lo), "=f"(hi) : "l"(v));
}
__device__ __forceinline__ unsigned h2_bits(__half2 h) {
    unsigned r;
    asm("mov.b32 %0, %1;" : "=r"(r) : "r"(*reinterpret_cast<unsigned*>(&h)));
    return r;
}

// ---------------- setup: zero counters + parallel dtype sniff ----------------
// int64 indices => odd 32-bit words of edge buffer are all zero.
__global__ void k_setup(const unsigned* __restrict__ e) {
    int i = blockIdx.x * blockDim.x + threadIdx.x;
    if (i < N_NODES) g_deg[i] = 0;
    if (i < NG * HID) g_pool[i] = 0.f;
    if (i < NG) g_cnt[i] = 0.f;
    if (blockIdx.x == 0 && threadIdx.x < 32) {
        unsigned nz = e[2 * threadIdx.x + 1] | e[2 * (threadIdx.x + 32) + 1];
        unsigned any = __ballot_sync(0xffffffffu, nz != 0u);
        if (threadIdx.x == 0) g_is64 = (any == 0u);
    }
}

// ---------------- in-degree count over dst (edges only) ----------------
__global__ void k_degcount(const void* __restrict__ ei) {
    int i = blockIdx.x * blockDim.x + threadIdx.x;
    if (i < N_EDGES) {
        int d = load_idx(ei, (long long)N_EDGES + i, g_is64);
        atomicAdd(&g_deg[d], 1);
    }
}

// ---------------- scan stage 1: per-block degree sums ----------------
__global__ __launch_bounds__(SCAN_B) void k_blocksum() {
    __shared__ int ws[32];
    const int t = threadIdx.x;
    const int i = blockIdx.x * SCAN_B + t;
    int v = (i < N_NODES) ? g_deg[i] : 0;
#pragma unroll
    for (int o = 16; o > 0; o >>= 1) v += __shfl_down_sync(0xffffffffu, v, o);
    if ((t & 31) == 0) ws[t >> 5] = v;
    __syncthreads();
    if (t < 32) {
        int s = ws[t];
#pragma unroll
        for (int o = 16; o > 0; o >>= 1) s += __shfl_down_sync(0xffffffffu, s, o);
        if (t == 0) g_bsum[blockIdx.x] = s;
    }
}

// ---------------- scan stage 2: exclusive scan of 98 block sums ----------------
__global__ __launch_bounds__(128) void k_scanb() {
    __shared__ int sh[128];
    const int t = threadIdx.x;
    sh[t] = (t < SCAN_NB) ? g_bsum[t] : 0;
    __syncthreads();
#pragma unroll
    for (int o = 1; o < 128; o <<= 1) {
        int v = (t >= o) ? sh[t - o] : 0;
        __syncthreads();
        sh[t] += v;
        __syncthreads();
    }
    if (t < SCAN_NB) g_boff[t] = (t == 0) ? 0 : sh[t - 1];
}

// ---------------- scan stage 3: block-local exclusive scan + emit ----------------
__global__ __launch_bounds__(SCAN_B) void k_rowstart() {
    __shared__ int ws[32];
    const int t = threadIdx.x;
    const int lane = t & 31, wid = t >> 5;
    const int i = blockIdx.x * SCAN_B + t;
    int d = (i < N_NODES) ? g_deg[i] : 0;
    int v = d;
#pragma unroll
    for (int o = 1; o < 32; o <<= 1) {
        int u = __shfl_up_sync(0xffffffffu, v, o);
        if (lane >= o) v += u;
    }
    if (lane == 31) ws[wid] = v;
    __syncthreads();
    if (t < 32) {
        int w = ws[t];
#pragma unroll
        for (int o = 1; o < 32; o <<= 1) {
            int u = __shfl_up_sync(0xffffffffu, w, o);
            if (t >= o) w += u;
        }
        ws[t] = w;
    }
    __syncthreads();
    int ex = (v - d) + (wid ? ws[wid - 1] : 0) + g_boff[blockIdx.x];
    if (i < N_NODES) {
        g_rowstart[i] = ex;
        g_cursor[i]   = ex;
        g_dinv[i]     = rsqrtf((float)(d + 1));    // +1 self loop
    }
}

// ---------------- CSR fill: bucket src by dst ----------------
__global__ void k_fill(const void* __restrict__ ei) {
    int i = blockIdx.x * blockDim.x + threadIdx.x;
    if (i < N_EDGES) {
        const int is64 = g_is64;
        int s = load_idx(ei, i, is64);
        int d = load_idx(ei, (long long)N_EDGES + i, is64);
        int pos = atomicAdd(&g_cursor[d], 1);
        g_esrc[pos] = s;
    }
}

// ---------------- GEMM: hs = (x @ W) * dinv, packed f32x2 FMA, fp16 out -------
// block tile: 128 rows x 64 cols; thread: 4 rows (stride 32) x 8 cols.
__global__ __launch_bounds__(256) void k_gemm(const float* __restrict__ x,
                                              const float* __restrict__ W) {
    __shared__ __align__(16) float Ws[32 * 64];       // [k][c]  8KB
    __shared__ __align__(16) float Xs[128 * 36];      // [row][k] stride 36, 18KB

    const int t    = threadIdx.x;
    const int ty   = t >> 3;            // 0..31
    const int tx   = t & 7;             // 0..7
    const int row0 = blockIdx.x * 128;

    u64 acc[4][4];
#pragma unroll
    for (int r = 0; r < 4; r++)
#pragma unroll
        for (int j = 0; j < 4; j++) acc[r][j] = 0ull;

    for (int ph = 0; ph < 4; ph++) {
        __syncthreads();
#pragma unroll
        for (int i = t; i < 512; i += 256) {
            ((float4*)Ws)[i] = ((const float4*)(W + ph * 32 * 64))[i];
        }
#pragma unroll
        for (int i = t; i < 1024; i += 256) {
            int rr = i >> 3, c4 = i & 7;
            int gr = row0 + rr;
            if (gr >= N_NODES) gr = N_NODES - 1;
            float4 v = ((const float4*)(x + (size_t)gr * IN_CH + ph * 32))[c4];
            *(float4*)(Xs + rr * 36 + c4 * 4) = v;
        }
        __syncthreads();

#pragma unroll
        for (int k = 0; k < 32; k++) {
            u64 xx[4];
#pragma unroll
            for (int r = 0; r < 4; r++)
                xx[r] = pack2(Xs[(ty + 32 * r) * 36 + k]);
            ulonglong2 wA = *(const ulonglong2*)(Ws + k * 64 + tx * 8);
            ulonglong2 wB = *(const ulonglong2*)(Ws + k * 64 + tx * 8 + 4);
#pragma unroll
            for (int r = 0; r < 4; r++) {
                fma2(acc[r][0], xx[r], wA.x);
                fma2(acc[r][1], xx[r], wA.y);
                fma2(acc[r][2], xx[r], wB.x);
                fma2(acc[r][3], xx[r], wB.y);
            }
        }
    }

#pragma unroll
    for (int r = 0; r < 4; r++) {
        int row = row0 + ty + 32 * r;
        if (row < N_NODES) {
            float dv = g_dinv[row];
            float o[8];
#pragma unroll
            for (int j = 0; j < 4; j++) unpack2(acc[r][j], o[2 * j], o[2 * j + 1]);
            __half2 h0 = __floats2half2_rn(o[0] * dv, o[1] * dv);
            __half2 h1 = __floats2half2_rn(o[2] * dv, o[3] * dv);
            __half2 h2 = __floats2half2_rn(o[4] * dv, o[5] * dv);
            __half2 h3 = __floats2half2_rn(o[6] * dv, o[7] * dv);
            uint4 pk;
            pk.x = h2_bits(h0); pk.y = h2_bits(h1);
            pk.z = h2_bits(h2); pk.w = h2_bits(h3);
            *(uint4*)(g_hs + (size_t)row * HID + tx * 8) = pk;
        }
    }
}

// ---------------- aggregate + relu + pool: warp per node, lane owns half2 -----
__global__ __launch_bounds__(256) void k_agg(const void* __restrict__ batch,
                                             const float* __restrict__ bconv) {
    const int gt   = blockIdx.x * blockDim.x + threadIdx.x;
    const int node = gt >> 5;
    const int lane = gt & 31;
    const __half2* hp = (const __half2*)g_hs;   // row stride 32 half2

    // self-loop term
    float2 sum = __half22float2(hp[(size_t)node * 32 + lane]);

    const int rs = g_rowstart[node];
    const int d  = g_deg[node];
    const int* ep = g_esrc + rs;

    int e = 0;
    for (; e + 8 <= d; e += 8) {
        int s[8];
#pragma unroll
        for (int j = 0; j < 8; j++) s[j] = __ldg(ep + e + j);
        float2 p0 = make_float2(0.f, 0.f), p1 = p0, p2 = p0, p3 = p0;
#pragma unroll
        for (int j = 0; j < 8; j += 4) {
            float2 v0 = __half22float2(hp[(size_t)s[j + 0] * 32 + lane]);
            float2 v1 = __half22float2(hp[(size_t)s[j + 1] * 32 + lane]);
            float2 v2 = __half22float2(hp[(size_t)s[j + 2] * 32 + lane]);
            float2 v3 = __half22float2(hp[(size_t)s[j + 3] * 32 + lane]);
            p0.x += v0.x; p0.y += v0.y;
            p1.x += v1.x; p1.y += v1.y;
            p2.x += v2.x; p2.y += v2.y;
            p3.x += v3.x; p3.y += v3.y;
        }
        sum.x += (p0.x + p1.x) + (p2.x + p3.x);
        sum.y += (p0.y + p1.y) + (p2.y + p3.y);
    }
    for (; e < d; e++) {
        float2 v = __half22float2(hp[(size_t)__ldg(ep + e) * 32 + lane]);
        sum.x += v.x; sum.y += v.y;
    }

    const float dv = g_dinv[node];
    float2 b = ((const float2*)bconv)[lane];
    float hx = fmaxf(fmaf(dv, sum.x, b.x), 0.f);
    float hy = fmaxf(fmaf(dv, sum.y, b.y), 0.f);

    const int g = load_idx(batch, node, g_is64);
    float* pp = g_pool + g * HID + lane * 2;
    asm volatile("red.global.add.v2.f32 [%0], {%1, %2};"
                 :: "l"(pp), "f"(hx), "f"(hy) : "memory");
    if (lane == 0) atomicAdd(&g_cnt[g], 1.0f);
}

// ---------------- final: out = (pool/cnt) @ W_lin + b_lin ----------------
__global__ __launch_bounds__(256) void k_final(const float* __restrict__ Wl,
                                               const float* __restrict__ bl,
                                               float* __restrict__ out) {
    __shared__ float sW[HID * OUTC];
    __shared__ float sb[OUTC];
    const int t = threadIdx.x;
    for (int i = t; i < HID * OUTC; i += 256) sW[i] = Wl[i];
    if (t < OUTC) sb[t] = bl[t];
    __syncthreads();

    const float inv = 1.f / fmaxf(g_cnt[t], 1.f);
    float acc[OUTC];
#pragma unroll
    for (int j = 0; j < OUTC; j++) acc[j] = sb[j];
#pragma unroll 4
    for (int c = 0; c < HID; c++) {
        float p = g_pool[t * HID + c] * inv;
#pragma unroll
        for (int j = 0; j < OUTC; j++) acc[j] = fmaf(p, sW[c * OUTC + j], acc[j]);
    }
#pragma unroll
    for (int j = 0; j < OUTC; j++) out[t * OUTC + j] = acc[j];
}

// ---------------- launch ----------------
extern "C" void kernel_launch(void* const* d_in, const int* in_sizes, int n_in,
                              void* d_out, int out_size) {
    const float* x     = (const float*)d_in[0];
    const void*  ei    = d_in[1];
    const void*  batch = d_in[2];
    const float* Wc    = (const float*)d_in[3];
    const float* bc    = (const float*)d_in[4];
    const float* Wl    = (const float*)d_in[5];
    const float* bl    = (const float*)d_in[6];
    float*       out   = (float*)d_out;

    k_setup    <<<(N_NODES + 255) / 256, 256>>>((const unsigned*)ei);
    k_degcount <<<(N_EDGES + 255) / 256, 256>>>(ei);
    k_blocksum <<<SCAN_NB, SCAN_B>>>();
    k_scanb    <<<1, 128>>>();
    k_rowstart <<<SCAN_NB, SCAN_B>>>();
    k_fill     <<<(N_EDGES + 255) / 256, 256>>>(ei);
    k_gemm     <<<(N_NODES + 127) / 128, 256>>>(x, Wc);
    k_agg      <<<(N_NODES * 32) / 256, 256>>>(batch, bc);
    k_final    <<<1, 256>>>(Wl, bl, out);
}

// round 6
// speedup vs baseline: 2.2881x; 1.1236x over previous
#include <cuda_runtime.h>
#include <cuda_fp16.h>
#include <cstdint>

#define N_NODES 100000
#define N_EDGES 1600000
#define IN_CH   128
#define HID     64
#define NG      256
#define OUTC    10

#define SCAN_B  1024
#define SCAN_NB ((N_NODES + SCAN_B - 1) / SCAN_B)   // 98

typedef unsigned long long u64;

// ---------------- scratch (device globals; no allocation) ----------------
__device__ int    g_is64;
__device__ __align__(16) int    g_deg[N_NODES];
__device__ __align__(16) int    g_rowstart[N_NODES];
__device__ __align__(16) int    g_cursor[N_NODES];
__device__ __align__(16) int    g_esrc[N_EDGES];     // CSR: src per edge, bucketed by dst
__device__ __align__(16) int    g_bsum[SCAN_NB];
__device__ volatile int         g_sflag[SCAN_NB];
__device__ __align__(16) float  g_dinv[N_NODES];
__device__ __align__(16) __half g_hs [(size_t)N_NODES * HID];  // (x@W)*dinv, fp16
__device__ __align__(16) float  g_pool[NG * HID];
__device__ __align__(16) float  g_cnt [NG];

// index loader handling int64-vs-int32 edge/batch buffers
__device__ __forceinline__ int load_idx(const void* p, long long i, int is64) {
    if (is64) return (int)((const long long*)p)[i];
    return ((const int*)p)[i];
}

__device__ __forceinline__ void fma2(u64& d, u64 a, u64 b) {
    asm("fma.rn.f32x2 %0, %1, %2, %0;" : "+l"(d) : "l"(a), "l"(b));
}
__device__ __forceinline__ u64 pack2(float v) {
    u64 r; asm("mov.b64 %0, {%1, %1};" : "=l"(r) : "f"(v)); return r;
}
__device__ __forceinline__ void unpack2(u64 v, float& lo, float& hi) {
    asm("mov.b64 {%0, %1}, %2;" : "=f"(lo), "=f"(hi) : "l"(v));
}
__device__ __forceinline__ unsigned h2_bits(__half2 h) {
    return *reinterpret_cast<unsigned*>(&h);
}
__device__ __forceinline__ float2 h2f2(unsigned b) {
    __half2 h = *reinterpret_cast<__half2*>(&b);
    return __half22float2(h);
}

// ---------------- setup: zero counters/flags + parallel dtype sniff ----------
__global__ void k_setup(const unsigned* __restrict__ e) {
    int i = blockIdx.x * blockDim.x + threadIdx.x;
    if (i < N_NODES) g_deg[i] = 0;
    if (i < NG * HID) g_pool[i] = 0.f;
    if (i < NG) g_cnt[i] = 0.f;
    if (i < SCAN_NB) g_sflag[i] = 0;
    if (blockIdx.x == 0 && threadIdx.x < 32) {
        unsigned nz = e[2 * threadIdx.x + 1] | e[2 * (threadIdx.x + 32) + 1];
        unsigned any = __ballot_sync(0xffffffffu, nz != 0u);
        if (threadIdx.x == 0) g_is64 = (any == 0u);
    }
}

// ---------------- in-degree count over dst (edges only) ----------------
__global__ void k_degcount(const void* __restrict__ ei) {
    int i = blockIdx.x * blockDim.x + threadIdx.x;
    if (i < N_EDGES) {
        int d = load_idx(ei, (long long)N_EDGES + i, g_is64);
        atomicAdd(&g_deg[d], 1);
    }
}

// ---------------- fused scan: block scan + decoupled lookback + emit ---------
// 98 blocks x 1024, all resident (98 <= 148 SMs) so spin-poll is safe.
__global__ __launch_bounds__(SCAN_B) void k_scanfused() {
    __shared__ int ws[32];
    __shared__ int s_off;
    const int b = blockIdx.x;
    const int t = threadIdx.x;
    const int lane = t & 31, wid = t >> 5;
    const int i = b * SCAN_B + t;
    int d = (i < N_NODES) ? g_deg[i] : 0;
    int v = d;
#pragma unroll
    for (int o = 1; o < 32; o <<= 1) {
        int u = __shfl_up_sync(0xffffffffu, v, o);
        if (lane >= o) v += u;
    }
    if (lane == 31) ws[wid] = v;
    __syncthreads();
    if (t < 32) {
        int w = ws[t];
#pragma unroll
        for (int o = 1; o < 32; o <<= 1) {
            int u = __shfl_up_sync(0xffffffffu, w, o);
            if (t >= o) w += u;
        }
        ws[t] = w;
    }
    __syncthreads();
    // publish this block's aggregate
    if (t == 0) {
        g_bsum[b] = ws[31];
        __threadfence();
        g_sflag[b] = 1;
    }
    // lookback: warp 0 sums aggregates of blocks [0, b)
    if (t < 32) {
        int off = 0;
        for (int base = 0; base < b; base += 32) {
            int idx = base + lane;
            bool need = (idx < b);
            while (__ballot_sync(0xffffffffu, need && (g_sflag[idx] == 0))) { }
            if (need) off += *(volatile int*)&g_bsum[idx];
        }
#pragma unroll
        for (int o = 16; o > 0; o >>= 1) off += __shfl_down_sync(0xffffffffu, off, o);
        if (lane == 0) s_off = off;
    }
    __syncthreads();
    int ex = (v - d) + (wid ? ws[wid - 1] : 0) + s_off;
    if (i < N_NODES) {
        g_rowstart[i] = ex;
        g_cursor[i]   = ex;
        g_dinv[i]     = rsqrtf((float)(d + 1));    // +1 self loop
    }
}

// ---------------- CSR fill: bucket src by dst ----------------
__global__ void k_fill(const void* __restrict__ ei) {
    int i = blockIdx.x * blockDim.x + threadIdx.x;
    if (i < N_EDGES) {
        const int is64 = g_is64;
        int s = load_idx(ei, i, is64);
        int d = load_idx(ei, (long long)N_EDGES + i, is64);
        int pos = atomicAdd(&g_cursor[d], 1);
        g_esrc[pos] = s;
    }
}

// ---------------- GEMM: hs = (x @ W) * dinv, packed f32x2 FMA, fp16 out -------
__global__ __launch_bounds__(256) void k_gemm(const float* __restrict__ x,
                                              const float* __restrict__ W) {
    __shared__ __align__(16) float Ws[32 * 64];       // [k][c]  8KB
    __shared__ __align__(16) float Xs[128 * 36];      // [row][k] stride 36, 18KB

    const int t    = threadIdx.x;
    const int ty   = t >> 3;            // 0..31
    const int tx   = t & 7;             // 0..7
    const int row0 = blockIdx.x * 128;

    u64 acc[4][4];
#pragma unroll
    for (int r = 0; r < 4; r++)
#pragma unroll
        for (int j = 0; j < 4; j++) acc[r][j] = 0ull;

    for (int ph = 0; ph < 4; ph++) {
        __syncthreads();
#pragma unroll
        for (int i = t; i < 512; i += 256) {
            ((float4*)Ws)[i] = ((const float4*)(W + ph * 32 * 64))[i];
        }
#pragma unroll
        for (int i = t; i < 1024; i += 256) {
            int rr = i >> 3, c4 = i & 7;
            int gr = row0 + rr;
            if (gr >= N_NODES) gr = N_NODES - 1;
            float4 v = ((const float4*)(x + (size_t)gr * IN_CH + ph * 32))[c4];
            *(float4*)(Xs + rr * 36 + c4 * 4) = v;
        }
        __syncthreads();

#pragma unroll
        for (int k = 0; k < 32; k++) {
            u64 xx[4];
#pragma unroll
            for (int r = 0; r < 4; r++)
                xx[r] = pack2(Xs[(ty + 32 * r) * 36 + k]);
            ulonglong2 wA = *(const ulonglong2*)(Ws + k * 64 + tx * 8);
            ulonglong2 wB = *(const ulonglong2*)(Ws + k * 64 + tx * 8 + 4);
#pragma unroll
            for (int r = 0; r < 4; r++) {
                fma2(acc[r][0], xx[r], wA.x);
                fma2(acc[r][1], xx[r], wA.y);
                fma2(acc[r][2], xx[r], wB.x);
                fma2(acc[r][3], xx[r], wB.y);
            }
        }
    }

#pragma unroll
    for (int r = 0; r < 4; r++) {
        int row = row0 + ty + 32 * r;
        if (row < N_NODES) {
            float dv = g_dinv[row];
            float o[8];
#pragma unroll
            for (int j = 0; j < 4; j++) unpack2(acc[r][j], o[2 * j], o[2 * j + 1]);
            __half2 h0 = __floats2half2_rn(o[0] * dv, o[1] * dv);
            __half2 h1 = __floats2half2_rn(o[2] * dv, o[3] * dv);
            __half2 h2 = __floats2half2_rn(o[4] * dv, o[5] * dv);
            __half2 h3 = __floats2half2_rn(o[6] * dv, o[7] * dv);
            uint4 pk;
            pk.x = h2_bits(h0); pk.y = h2_bits(h1);
            pk.z = h2_bits(h2); pk.w = h2_bits(h3);
            *(uint4*)(g_hs + (size_t)row * HID + tx * 8) = pk;
        }
    }
}

// ---------------- aggregate + relu + pool: 2 nodes/warp, 16 lanes own uint2 ---
__global__ __launch_bounds__(256) void k_agg(const void* __restrict__ batch,
                                             const float* __restrict__ bconv) {
    const int gt   = blockIdx.x * blockDim.x + threadIdx.x;
    const int warp = gt >> 5;
    const int lane = gt & 31;
    const int node = warp * 2 + (lane >> 4);
    const int hl   = lane & 15;
    const uint2* hp = (const uint2*)g_hs;    // row = 16 uint2 (128B)

    // self-loop term
    uint2 u = hp[(size_t)node * 16 + hl];
    float2 sa = h2f2(u.x);
    float2 sb = h2f2(u.y);

    const int rs = g_rowstart[node];
    const int d  = g_deg[node];
    const int* ep = g_esrc + rs;

    int e = 0;
    for (; e + 8 <= d; e += 8) {
        int s[8];
#pragma unroll
        for (int j = 0; j < 8; j++) s[j] = __ldg(ep + e + j);
        float2 pa0 = make_float2(0.f, 0.f), pa1 = pa0, pa2 = pa0, pa3 = pa0;
        float2 pb0 = pa0, pb1 = pa0, pb2 = pa0, pb3 = pa0;
#pragma unroll
        for (int j = 0; j < 8; j += 4) {
            uint2 v0 = hp[(size_t)s[j + 0] * 16 + hl];
            uint2 v1 = hp[(size_t)s[j + 1] * 16 + hl];
            uint2 v2 = hp[(size_t)s[j + 2] * 16 + hl];
            uint2 v3 = hp[(size_t)s[j + 3] * 16 + hl];
            float2 a0 = h2f2(v0.x), b0 = h2f2(v0.y);
            float2 a1 = h2f2(v1.x), b1 = h2f2(v1.y);
            float2 a2 = h2f2(v2.x), b2 = h2f2(v2.y);
            float2 a3 = h2f2(v3.x), b3 = h2f2(v3.y);
            pa0.x += a0.x; pa0.y += a0.y; pb0.x += b0.x; pb0.y += b0.y;
            pa1.x += a1.x; pa1.y += a1.y; pb1.x += b1.x; pb1.y += b1.y;
            pa2.x += a2.x; pa2.y += a2.y; pb2.x += b2.x; pb2.y += b2.y;
            pa3.x += a3.x; pa3.y += a3.y; pb3.x += b3.x; pb3.y += b3.y;
        }
        sa.x += (pa0.x + pa1.x) + (pa2.x + pa3.x);
        sa.y += (pa0.y + pa1.y) + (pa2.y + pa3.y);
        sb.x += (pb0.x + pb1.x) + (pb2.x + pb3.x);
        sb.y += (pb0.y + pb1.y) + (pb2.y + pb3.y);
    }
    for (; e < d; e++) {
        uint2 v = hp[(size_t)__ldg(ep + e) * 16 + hl];
        float2 a = h2f2(v.x), b = h2f2(v.y);
        sa.x += a.x; sa.y += a.y; sb.x += b.x; sb.y += b.y;
    }

    const float dv = g_dinv[node];
    float4 bb = ((const float4*)bconv)[hl];
    float h0 = fmaxf(fmaf(dv, sa.x, bb.x), 0.f);
    float h1 = fmaxf(fmaf(dv, sa.y, bb.y), 0.f);
    float h2 = fmaxf(fmaf(dv, sb.x, bb.z), 0.f);
    float h3 = fmaxf(fmaf(dv, sb.y, bb.w), 0.f);

    const int g = load_idx(batch, node, g_is64);
    float* pp = g_pool + g * HID + hl * 4;
    asm volatile("red.global.add.v4.f32 [%0], {%1, %2, %3, %4};"
                 :: "l"(pp), "f"(h0), "f"(h1), "f"(h2), "f"(h3) : "memory");
    if (hl == 0) atomicAdd(&g_cnt[g], 1.0f);
}

// ---------------- final: out = (pool/cnt) @ W_lin + b_lin ----------------
__global__ __launch_bounds__(256) void k_final(const float* __restrict__ Wl,
                                               const float* __restrict__ bl,
                                               float* __restrict__ out) {
    __shared__ float sW[HID * OUTC];
    __shared__ float sb[OUTC];
    const int t = threadIdx.x;
    for (int i = t; i < HID * OUTC; i += 256) sW[i] = Wl[i];
    if (t < OUTC) sb[t] = bl[t];
    __syncthreads();

    const float inv = 1.f / fmaxf(g_cnt[t], 1.f);
    float acc[OUTC];
#pragma unroll
    for (int j = 0; j < OUTC; j++) acc[j] = sb[j];
#pragma unroll 4
    for (int c = 0; c < HID; c++) {
        float p = g_pool[t * HID + c] * inv;
#pragma unroll
        for (int j = 0; j < OUTC; j++) acc[j] = fmaf(p, sW[c * OUTC + j], acc[j]);
    }
#pragma unroll
    for (int j = 0; j < OUTC; j++) out[t * OUTC + j] = acc[j];
}

// ---------------- launch ----------------
extern "C" void kernel_launch(void* const* d_in, const int* in_sizes, int n_in,
                              void* d_out, int out_size) {
    const float* x     = (const float*)d_in[0];
    const void*  ei    = d_in[1];
    const void*  batch = d_in[2];
    const float* Wc    = (const float*)d_in[3];
    const float* bc    = (const float*)d_in[4];
    const float* Wl    = (const float*)d_in[5];
    const float* bl    = (const float*)d_in[6];
    float*       out   = (float*)d_out;

    k_setup     <<<(N_NODES + 255) / 256, 256>>>((const unsigned*)ei);
    k_degcount  <<<(N_EDGES + 255) / 256, 256>>>(ei);
    k_scanfused <<<SCAN_NB, SCAN_B>>>();
    k_fill      <<<(N_EDGES + 255) / 256, 256>>>(ei);
    k_gemm      <<<(N_NODES + 127) / 128, 256>>>(x, Wc);
    k_agg       <<<(N_NODES / 2 * 32) / 256, 256>>>(batch, bc);
    k_final     <<<1, 256>>>(Wl, bl, out);
}

// round 7
// speedup vs baseline: 3.0498x; 1.3329x over previous
#include <cuda_runtime.h>
#include <cuda_fp16.h>
#include <cstdint>

#define N_NODES 100000
#define N_EDGES 1600000
#define IN_CH   128
#define HID     64
#define NG      256
#define OUTC    10

#define SCAN_B  1024
#define SCAN_NB ((N_NODES + SCAN_B - 1) / SCAN_B)   // 98

typedef unsigned long long u64;

// ---------------- scratch (device globals; no allocation) ----------------
__device__ int    g_is64;
__device__ __align__(16) int    g_deg[N_NODES];
__device__ __align__(16) int    g_rowstart[N_NODES];
__device__ __align__(16) int    g_cursor[N_NODES];
__device__ __align__(16) int    g_esrc[N_EDGES];     // CSR: src per edge, bucketed by dst
__device__ __align__(16) int    g_bsum[SCAN_NB];
__device__ volatile int         g_sflag[SCAN_NB];
__device__ __align__(16) float  g_dinv[N_NODES];
__device__ __align__(16) __half g_hs [(size_t)N_NODES * HID];  // (x@W)*dinv, fp16
__device__ __align__(16) float  g_pool[NG * HID];
__device__ __align__(16) float  g_cnt [NG];

// index loader handling int64-vs-int32 edge/batch buffers
__device__ __forceinline__ int load_idx(const void* p, long long i, int is64) {
    if (is64) return (int)((const long long*)p)[i];
    return ((const int*)p)[i];
}

__device__ __forceinline__ unsigned h2_bits(__half2 h) {
    return *reinterpret_cast<unsigned*>(&h);
}
__device__ __forceinline__ float2 h2f2(unsigned b) {
    __half2 h = *reinterpret_cast<__half2*>(&b);
    return __half22float2(h);
}
__device__ __forceinline__ unsigned f2tf(float f) {
    unsigned r; asm("cvt.rna.tf32.f32 %0, %1;" : "=r"(r) : "f"(f)); return r;
}

// ---------------- setup: zero counters/flags + parallel dtype sniff ----------
__global__ void k_setup(const unsigned* __restrict__ e) {
    int i = blockIdx.x * blockDim.x + threadIdx.x;
    if (i < N_NODES) g_deg[i] = 0;
    if (i < NG * HID) g_pool[i] = 0.f;
    if (i < NG) g_cnt[i] = 0.f;
    if (i < SCAN_NB) g_sflag[i] = 0;
    if (blockIdx.x == 0 && threadIdx.x < 32) {
        unsigned nz = e[2 * threadIdx.x + 1] | e[2 * (threadIdx.x + 32) + 1];
        unsigned any = __ballot_sync(0xffffffffu, nz != 0u);
        if (threadIdx.x == 0) g_is64 = (any == 0u);
    }
}

// ---------------- in-degree count over dst (edges only) ----------------
__global__ void k_degcount(const void* __restrict__ ei) {
    int i = blockIdx.x * blockDim.x + threadIdx.x;
    if (i < N_EDGES) {
        int d = load_idx(ei, (long long)N_EDGES + i, g_is64);
        atomicAdd(&g_deg[d], 1);
    }
}

// ---------------- fused scan: block scan + decoupled lookback + emit ---------
__global__ __launch_bounds__(SCAN_B) void k_scanfused() {
    __shared__ int ws[32];
    __shared__ int s_off;
    const int b = blockIdx.x;
    const int t = threadIdx.x;
    const int lane = t & 31, wid = t >> 5;
    const int i = b * SCAN_B + t;
    int d = (i < N_NODES) ? g_deg[i] : 0;
    int v = d;
#pragma unroll
    for (int o = 1; o < 32; o <<= 1) {
        int u = __shfl_up_sync(0xffffffffu, v, o);
        if (lane >= o) v += u;
    }
    if (lane == 31) ws[wid] = v;
    __syncthreads();
    if (t < 32) {
        int w = ws[t];
#pragma unroll
        for (int o = 1; o < 32; o <<= 1) {
            int u = __shfl_up_sync(0xffffffffu, w, o);
            if (t >= o) w += u;
        }
        ws[t] = w;
    }
    __syncthreads();
    if (t == 0) {
        g_bsum[b] = ws[31];
        __threadfence();
        g_sflag[b] = 1;
    }
    if (t < 32) {
        int off = 0;
        for (int base = 0; base < b; base += 32) {
            int idx = base + lane;
            bool need = (idx < b);
            while (__ballot_sync(0xffffffffu, need && (g_sflag[idx] == 0))) { }
            if (need) off += *(volatile int*)&g_bsum[idx];
        }
#pragma unroll
        for (int o = 16; o > 0; o >>= 1) off += __shfl_down_sync(0xffffffffu, off, o);
        if (lane == 0) s_off = off;
    }
    __syncthreads();
    int ex = (v - d) + (wid ? ws[wid - 1] : 0) + s_off;
    if (i < N_NODES) {
        g_rowstart[i] = ex;
        g_cursor[i]   = ex;
        g_dinv[i]     = rsqrtf((float)(d + 1));    // +1 self loop
    }
}

// ---------------- GEMM: hs = (x @ W) * dinv, tf32 tensor cores, fp16 out ------
// block tile 128x64, 8 warps in 4x2 grid, warp tile 32x32 (2 m-tiles x 4 n-tiles
// of m16n8k8). K=128 in 4 phases of 32.
__global__ __launch_bounds__(256) void k_gemm(const float* __restrict__ x,
                                              const float* __restrict__ W) {
    __shared__ __align__(16) float Xs[128 * 36];   // [row][k], stride 36 -> conflict-free frags
    __shared__ __align__(16) float Wsm[32 * 72];   // [k][n],   stride 72 -> conflict-free frags

    const int t      = threadIdx.x;
    const int wid    = t >> 5;
    const int lane   = t & 31;
    const int warp_m = wid & 3;           // 0..3  (32 rows each)
    const int warp_n = wid >> 2;          // 0..1  (32 cols each)
    const int g      = lane >> 2;         // groupID 0..7
    const int tig    = lane & 3;          // thread-in-group 0..3
    const int row0   = blockIdx.x * 128;

    float c[2][4][4];
#pragma unroll
    for (int mt = 0; mt < 2; mt++)
#pragma unroll
        for (int nt = 0; nt < 4; nt++)
#pragma unroll
            for (int j = 0; j < 4; j++) c[mt][nt][j] = 0.f;

    for (int ph = 0; ph < 4; ph++) {
        __syncthreads();
        // W slab: 32 k-rows x 64 cols = 512 float4
#pragma unroll
        for (int i = t; i < 512; i += 256) {
            int kk = i >> 4, n4 = i & 15;
            float4 v = ((const float4*)(W + (size_t)(ph * 32 + kk) * HID))[n4];
            *(float4*)(Wsm + kk * 72 + n4 * 4) = v;
        }
        // X tile: 128 rows x 32 k = 1024 float4
#pragma unroll
        for (int i = t; i < 1024; i += 256) {
            int rr = i >> 3, k4 = i & 7;
            int gr = row0 + rr;
            if (gr >= N_NODES) gr = N_NODES - 1;
            float4 v = ((const float4*)(x + (size_t)gr * IN_CH + ph * 32))[k4];
            *(float4*)(Xs + rr * 36 + k4 * 4) = v;
        }
        __syncthreads();

#pragma unroll
        for (int ks = 0; ks < 4; ks++) {
            const int k_off = ks * 8;
            unsigned a[2][4], bfr[4][2];
#pragma unroll
            for (int mt = 0; mt < 2; mt++) {
                int br = warp_m * 32 + mt * 16 + g;
                a[mt][0] = f2tf(Xs[br * 36 + k_off + tig]);
                a[mt][1] = f2tf(Xs[(br + 8) * 36 + k_off + tig]);
                a[mt][2] = f2tf(Xs[br * 36 + k_off + tig + 4]);
                a[mt][3] = f2tf(Xs[(br + 8) * 36 + k_off + tig + 4]);
            }
#pragma unroll
            for (int nt = 0; nt < 4; nt++) {
                int n_off = warp_n * 32 + nt * 8 + g;
                bfr[nt][0] = f2tf(Wsm[(k_off + tig) * 72 + n_off]);
                bfr[nt][1] = f2tf(Wsm[(k_off + tig + 4) * 72 + n_off]);
            }
#pragma unroll
            for (int mt = 0; mt < 2; mt++)
#pragma unroll
                for (int nt = 0; nt < 4; nt++) {
                    asm("mma.sync.aligned.m16n8k8.row.col.f32.tf32.tf32.f32 "
                        "{%0,%1,%2,%3}, {%4,%5,%6,%7}, {%8,%9}, {%0,%1,%2,%3};"
                        : "+f"(c[mt][nt][0]), "+f"(c[mt][nt][1]),
                          "+f"(c[mt][nt][2]), "+f"(c[mt][nt][3])
                        : "r"(a[mt][0]), "r"(a[mt][1]), "r"(a[mt][2]), "r"(a[mt][3]),
                          "r"(bfr[nt][0]), "r"(bfr[nt][1]));
                }
        }
    }

    // epilogue: scale by dinv, pack fp16, store
#pragma unroll
    for (int mt = 0; mt < 2; mt++) {
        int r0 = row0 + warp_m * 32 + mt * 16 + g;
        int r1 = r0 + 8;
        float dv0 = (r0 < N_NODES) ? g_dinv[r0] : 0.f;
        float dv1 = (r1 < N_NODES) ? g_dinv[r1] : 0.f;
#pragma unroll
        for (int nt = 0; nt < 4; nt++) {
            int col = warp_n * 32 + nt * 8 + tig * 2;
            if (r0 < N_NODES) {
                __half2 h = __floats2half2_rn(c[mt][nt][0] * dv0, c[mt][nt][1] * dv0);
                *(unsigned*)(g_hs + (size_t)r0 * HID + col) = h2_bits(h);
            }
            if (r1 < N_NODES) {
                __half2 h = __floats2half2_rn(c[mt][nt][2] * dv1, c[mt][nt][3] * dv1);
                *(unsigned*)(g_hs + (size_t)r1 * HID + col) = h2_bits(h);
            }
        }
    }
}

// ---------------- CSR fill: bucket src by dst ----------------
__global__ void k_fill(const void* __restrict__ ei) {
    int i = blockIdx.x * blockDim.x + threadIdx.x;
    if (i < N_EDGES) {
        const int is64 = g_is64;
        int s = load_idx(ei, i, is64);
        int d = load_idx(ei, (long long)N_EDGES + i, is64);
        int pos = atomicAdd(&g_cursor[d], 1);
        g_esrc[pos] = s;
    }
}

// ---------------- aggregate + relu + pool: 2 nodes/warp, 16 lanes own uint2 ---
__global__ __launch_bounds__(256) void k_agg(const void* __restrict__ batch,
                                             const float* __restrict__ bconv) {
    const int gt   = blockIdx.x * blockDim.x + threadIdx.x;
    const int warp = gt >> 5;
    const int lane = gt & 31;
    const int node = warp * 2 + (lane >> 4);
    const int hl   = lane & 15;
    const uint2* hp = (const uint2*)g_hs;    // row = 16 uint2 (128B)

    uint2 u = hp[(size_t)node * 16 + hl];
    float2 sa = h2f2(u.x);
    float2 sb = h2f2(u.y);

    const int rs = g_rowstart[node];
    const int d  = g_deg[node];
    const int* ep = g_esrc + rs;

    int e = 0;
    for (; e + 8 <= d; e += 8) {
        int s[8];
#pragma unroll
        for (int j = 0; j < 8; j++) s[j] = __ldg(ep + e + j);
        float2 pa0 = make_float2(0.f, 0.f), pa1 = pa0, pa2 = pa0, pa3 = pa0;
        float2 pb0 = pa0, pb1 = pa0, pb2 = pa0, pb3 = pa0;
#pragma unroll
        for (int j = 0; j < 8; j += 4) {
            uint2 v0 = hp[(size_t)s[j + 0] * 16 + hl];
            uint2 v1 = hp[(size_t)s[j + 1] * 16 + hl];
            uint2 v2 = hp[(size_t)s[j + 2] * 16 + hl];
            uint2 v3 = hp[(size_t)s[j + 3] * 16 + hl];
            float2 a0 = h2f2(v0.x), b0 = h2f2(v0.y);
            float2 a1 = h2f2(v1.x), b1 = h2f2(v1.y);
            float2 a2 = h2f2(v2.x), b2 = h2f2(v2.y);
            float2 a3 = h2f2(v3.x), b3 = h2f2(v3.y);
            pa0.x += a0.x; pa0.y += a0.y; pb0.x += b0.x; pb0.y += b0.y;
            pa1.x += a1.x; pa1.y += a1.y; pb1.x += b1.x; pb1.y += b1.y;
            pa2.x += a2.x; pa2.y += a2.y; pb2.x += b2.x; pb2.y += b2.y;
            pa3.x += a3.x; pa3.y += a3.y; pb3.x += b3.x; pb3.y += b3.y;
        }
        sa.x += (pa0.x + pa1.x) + (pa2.x + pa3.x);
        sa.y += (pa0.y + pa1.y) + (pa2.y + pa3.y);
        sb.x += (pb0.x + pb1.x) + (pb2.x + pb3.x);
        sb.y += (pb0.y + pb1.y) + (pb2.y + pb3.y);
    }
    for (; e < d; e++) {
        uint2 v = hp[(size_t)__ldg(ep + e) * 16 + hl];
        float2 a = h2f2(v.x), b = h2f2(v.y);
        sa.x += a.x; sa.y += a.y; sb.x += b.x; sb.y += b.y;
    }

    const float dv = g_dinv[node];
    float4 bb = ((const float4*)bconv)[hl];
    float h0 = fmaxf(fmaf(dv, sa.x, bb.x), 0.f);
    float h1 = fmaxf(fmaf(dv, sa.y, bb.y), 0.f);
    float h2 = fmaxf(fmaf(dv, sb.x, bb.z), 0.f);
    float h3 = fmaxf(fmaf(dv, sb.y, bb.w), 0.f);

    const int g = load_idx(batch, node, g_is64);
    float* pp = g_pool + g * HID + hl * 4;
    asm volatile("red.global.add.v4.f32 [%0], {%1, %2, %3, %4};"
                 :: "l"(pp), "f"(h0), "f"(h1), "f"(h2), "f"(h3) : "memory");
    if (hl == 0) atomicAdd(&g_cnt[g], 1.0f);
}

// ---------------- final: out = (pool/cnt) @ W_lin + b_lin ----------------
__global__ __launch_bounds__(256) void k_final(const float* __restrict__ Wl,
                                               const float* __restrict__ bl,
                                               float* __restrict__ out) {
    __shared__ float sW[HID * OUTC];
    __shared__ float sb[OUTC];
    const int t = threadIdx.x;
    for (int i = t; i < HID * OUTC; i += 256) sW[i] = Wl[i];
    if (t < OUTC) sb[t] = bl[t];
    __syncthreads();

    const float inv = 1.f / fmaxf(g_cnt[t], 1.f);
    float acc[OUTC];
#pragma unroll
    for (int j = 0; j < OUTC; j++) acc[j] = sb[j];
#pragma unroll 4
    for (int c = 0; c < HID; c++) {
        float p = g_pool[t * HID + c] * inv;
#pragma unroll
        for (int j = 0; j < OUTC; j++) acc[j] = fmaf(p, sW[c * OUTC + j], acc[j]);
    }
#pragma unroll
    for (int j = 0; j < OUTC; j++) out[t * OUTC + j] = acc[j];
}

// ---------------- launch ----------------
extern "C" void kernel_launch(void* const* d_in, const int* in_sizes, int n_in,
                              void* d_out, int out_size) {
    const float* x     = (const float*)d_in[0];
    const void*  ei    = d_in[1];
    const void*  batch = d_in[2];
    const float* Wc    = (const float*)d_in[3];
    const float* bc    = (const float*)d_in[4];
    const float* Wl    = (const float*)d_in[5];
    const float* bl    = (const float*)d_in[6];
    float*       out   = (float*)d_out;

    k_setup     <<<(N_NODES + 255) / 256, 256>>>((const unsigned*)ei);
    k_degcount  <<<(N_EDGES + 255) / 256, 256>>>(ei);
    k_scanfused <<<SCAN_NB, SCAN_B>>>();
    k_gemm      <<<(N_NODES + 127) / 128, 256>>>(x, Wc);   // index 3: profiled next round
    k_fill      <<<(N_EDGES + 255) / 256, 256>>>(ei);
    k_agg       <<<(N_NODES / 2 * 32) / 256, 256>>>(batch, bc);
    k_final     <<<1, 256>>>(Wl, bl, out);
}

// round 10
// speedup vs baseline: 4.0188x; 1.3177x over previous
#include <cuda_runtime.h>
#include <cuda_fp16.h>
#include <cstdint>

#define N_NODES 100000
#define N_EDGES 1600000
#define IN_CH   128
#define HID     64
#define NG      256
#define OUTC    10

#define SCAN_B  1024
#define SCAN_NB ((N_NODES + SCAN_B - 1) / SCAN_B)   // 98

typedef unsigned long long u64;

// ---------------- scratch (device globals; no allocation) ----------------
__device__ int    g_is64;
__device__ __align__(16) int    g_deg[N_NODES];
__device__ __align__(16) int    g_rowstart[N_NODES];
__device__ __align__(16) int    g_cursor[N_NODES];
__device__ __align__(16) int    g_esrc[N_EDGES];     // CSR: src per edge, bucketed by dst
__device__ __align__(16) int    g_bsum[SCAN_NB];
__device__ volatile int         g_sflag[SCAN_NB];
__device__ __align__(16) float  g_dinv[N_NODES];
__device__ __align__(16) __half g_hs [(size_t)N_NODES * HID];  // (x@W)*dinv, fp16
__device__ __align__(16) float  g_pool[NG * HID];
__device__ __align__(16) float  g_cnt [NG];

// index loader handling int64-vs-int32 edge/batch buffers
__device__ __forceinline__ int load_idx(const void* p, long long i, int is64) {
    if (is64) return (int)((const long long*)p)[i];
    return ((const int*)p)[i];
}

__device__ __forceinline__ unsigned h2_bits(__half2 h) {
    return *reinterpret_cast<unsigned*>(&h);
}
__device__ __forceinline__ float2 h2f2(unsigned b) {
    __half2 h = *reinterpret_cast<__half2*>(&b);
    return __half22float2(h);
}
__device__ __forceinline__ unsigned f2tf(float f) {
    unsigned r; asm("cvt.rna.tf32.f32 %0, %1;" : "=r"(r) : "f"(f)); return r;
}

// ---------------- setup: zero counters/flags + parallel dtype sniff ----------
__global__ void k_setup(const unsigned* __restrict__ e) {
    int i = blockIdx.x * blockDim.x + threadIdx.x;
    if (i < N_NODES) g_deg[i] = 0;
    if (i < NG * HID) g_pool[i] = 0.f;
    if (i < NG) g_cnt[i] = 0.f;
    if (i < SCAN_NB) g_sflag[i] = 0;
    if (blockIdx.x == 0 && threadIdx.x < 32) {
        unsigned nz = e[2 * threadIdx.x + 1] | e[2 * (threadIdx.x + 32) + 1];
        unsigned any = __ballot_sync(0xffffffffu, nz != 0u);
        if (threadIdx.x == 0) g_is64 = (any == 0u);
    }
}

// ---------------- in-degree count over dst (edges only) ----------------
__global__ void k_degcount(const void* __restrict__ ei) {
    int i = blockIdx.x * blockDim.x + threadIdx.x;
    if (i < N_EDGES) {
        int d = load_idx(ei, (long long)N_EDGES + i, g_is64);
        atomicAdd(&g_deg[d], 1);
    }
}

// ---------------- fused scan: block scan + decoupled lookback + emit ---------
__global__ __launch_bounds__(SCAN_B) void k_scanfused() {
    __shared__ int ws[32];
    __shared__ int s_off;
    const int b = blockIdx.x;
    const int t = threadIdx.x;
    const int lane = t & 31, wid = t >> 5;
    const int i = b * SCAN_B + t;
    int d = (i < N_NODES) ? g_deg[i] : 0;
    int v = d;
#pragma unroll
    for (int o = 1; o < 32; o <<= 1) {
        int u = __shfl_up_sync(0xffffffffu, v, o);
        if (lane >= o) v += u;
    }
    if (lane == 31) ws[wid] = v;
    __syncthreads();
    if (t < 32) {
        int w = ws[t];
#pragma unroll
        for (int o = 1; o < 32; o <<= 1) {
            int u = __shfl_up_sync(0xffffffffu, w, o);
            if (t >= o) w += u;
        }
        ws[t] = w;
    }
    __syncthreads();
    if (t == 0) {
        g_bsum[b] = ws[31];
        __threadfence();
        g_sflag[b] = 1;
    }
    if (t < 32) {
        int off = 0;
        for (int base = 0; base < b; base += 32) {
            int idx = base + lane;
            bool need = (idx < b);
            while (__ballot_sync(0xffffffffu, need && (g_sflag[idx] == 0))) { }
            if (need) off += *(volatile int*)&g_bsum[idx];
        }
#pragma unroll
        for (int o = 16; o > 0; o >>= 1) off += __shfl_down_sync(0xffffffffu, off, o);
        if (lane == 0) s_off = off;
    }
    __syncthreads();
    int ex = (v - d) + (wid ? ws[wid - 1] : 0) + s_off;
    if (i < N_NODES) {
        g_rowstart[i] = ex;
        g_cursor[i]   = ex;
        g_dinv[i]     = rsqrtf((float)(d + 1));    // +1 self loop
    }
}

// ---------------- GEMM: hs = (x @ W) * dinv, tf32 tensor cores, fp16 out ------
// Smem holds PRE-CONVERTED tf32 bits (cvt once at store, not per fragment load).
// block tile 128x64, 8 warps 4x2, warp tile 32x32; K=128 in 4 phases of 32.
__global__ __launch_bounds__(256) void k_gemm(const float* __restrict__ x,
                                              const float* __restrict__ W) {
    __shared__ __align__(16) unsigned Xs[128 * 36];   // tf32 bits, stride 36
    __shared__ __align__(16) unsigned Wsm[32 * 72];   // tf32 bits, stride 72

    const int t      = threadIdx.x;
    const int wid    = t >> 5;
    const int lane   = t & 31;
    const int warp_m = wid & 3;
    const int warp_n = wid >> 2;
    const int g      = lane >> 2;
    const int tig    = lane & 3;
    const int row0   = blockIdx.x * 128;

    float c[2][4][4];
#pragma unroll
    for (int mt = 0; mt < 2; mt++)
#pragma unroll
        for (int nt = 0; nt < 4; nt++)
#pragma unroll
            for (int j = 0; j < 4; j++) c[mt][nt][j] = 0.f;

    for (int ph = 0; ph < 4; ph++) {
        __syncthreads();
        // W slab: 32 k-rows x 64 cols, cvt to tf32 at store
#pragma unroll
        for (int i = t; i < 512; i += 256) {
            int kk = i >> 4, n4 = i & 15;
            float4 v = ((const float4*)(W + (size_t)(ph * 32 + kk) * HID))[n4];
            uint4 u = make_uint4(f2tf(v.x), f2tf(v.y), f2tf(v.z), f2tf(v.w));
            *(uint4*)(Wsm + kk * 72 + n4 * 4) = u;
        }
        // X tile: 128 rows x 32 k, cvt to tf32 at store
#pragma unroll
        for (int i = t; i < 1024; i += 256) {
            int rr = i >> 3, k4 = i & 7;
            int gr = row0 + rr;
            if (gr >= N_NODES) gr = N_NODES - 1;
            float4 v = ((const float4*)(x + (size_t)gr * IN_CH + ph * 32))[k4];
            uint4 u = make_uint4(f2tf(v.x), f2tf(v.y), f2tf(v.z), f2tf(v.w));
            *(uint4*)(Xs + rr * 36 + k4 * 4) = u;
        }
        __syncthreads();

#pragma unroll
        for (int ks = 0; ks < 4; ks++) {
            const int k_off = ks * 8;
            unsigned a[2][4], bfr[4][2];
#pragma unroll
            for (int mt = 0; mt < 2; mt++) {
                int br = warp_m * 32 + mt * 16 + g;
                a[mt][0] = Xs[br * 36 + k_off + tig];
                a[mt][1] = Xs[(br + 8) * 36 + k_off + tig];
                a[mt][2] = Xs[br * 36 + k_off + tig + 4];
                a[mt][3] = Xs[(br + 8) * 36 + k_off + tig + 4];
            }
#pragma unroll
            for (int nt = 0; nt < 4; nt++) {
                int n_off = warp_n * 32 + nt * 8 + g;
                bfr[nt][0] = Wsm[(k_off + tig) * 72 + n_off];
                bfr[nt][1] = Wsm[(k_off + tig + 4) * 72 + n_off];
            }
#pragma unroll
            for (int mt = 0; mt < 2; mt++)
#pragma unroll
                for (int nt = 0; nt < 4; nt++) {
                    asm("mma.sync.aligned.m16n8k8.row.col.f32.tf32.tf32.f32 "
                        "{%0,%1,%2,%3}, {%4,%5,%6,%7}, {%8,%9}, {%0,%1,%2,%3};"
                        : "+f"(c[mt][nt][0]), "+f"(c[mt][nt][1]),
                          "+f"(c[mt][nt][2]), "+f"(c[mt][nt][3])
                        : "r"(a[mt][0]), "r"(a[mt][1]), "r"(a[mt][2]), "r"(a[mt][3]),
                          "r"(bfr[nt][0]), "r"(bfr[nt][1]));
                }
        }
    }

    // epilogue: scale by dinv, pack fp16, store
#pragma unroll
    for (int mt = 0; mt < 2; mt++) {
        int r0 = row0 + warp_m * 32 + mt * 16 + g;
        int r1 = r0 + 8;
        float dv0 = (r0 < N_NODES) ? g_dinv[r0] : 0.f;
        float dv1 = (r1 < N_NODES) ? g_dinv[r1] : 0.f;
#pragma unroll
        for (int nt = 0; nt < 4; nt++) {
            int col = warp_n * 32 + nt * 8 + tig * 2;
            if (r0 < N_NODES) {
                __half2 h = __floats2half2_rn(c[mt][nt][0] * dv0, c[mt][nt][1] * dv0);
                *(unsigned*)(g_hs + (size_t)r0 * HID + col) = h2_bits(h);
            }
            if (r1 < N_NODES) {
                __half2 h = __floats2half2_rn(c[mt][nt][2] * dv1, c[mt][nt][3] * dv1);
                *(unsigned*)(g_hs + (size_t)r1 * HID + col) = h2_bits(h);
            }
        }
    }
}

// ---------------- CSR fill: bucket src by dst ----------------
__global__ void k_fill(const void* __restrict__ ei) {
    int i = blockIdx.x * blockDim.x + threadIdx.x;
    if (i < N_EDGES) {
        const int is64 = g_is64;
        int s = load_idx(ei, i, is64);
        int d = load_idx(ei, (long long)N_EDGES + i, is64);
        int pos = atomicAdd(&g_cursor[d], 1);
        g_esrc[pos] = s;
    }
}

// ---------------- aggregate + relu + smem-pooled reduction ----------------
// Block = 16 consecutive nodes (8 warps x 2). batch is sorted, so the block's
// graph ids span a tiny range: accumulate in a 16-slot smem pool, flush only
// used slots (cuts global red.v4 count ~10x).
__global__ __launch_bounds__(256) void k_agg(const void* __restrict__ batch,
                                             const float* __restrict__ bconv) {
    __shared__ __align__(16) float sp[16 * 64];   // slot-major pool accum
    __shared__ int scnt[16];
    __shared__ int sglo;

    const int t    = threadIdx.x;
    const int gt   = blockIdx.x * 256 + t;
    const int warp = gt >> 5;
    const int lane = gt & 31;
    const int node = warp * 2 + (lane >> 4);
    const int hl   = lane & 15;
    const int is64 = g_is64;
    const uint2* hp = (const uint2*)g_hs;    // row = 16 uint2 (128B)

    // init smem
    if (t == 0) sglo = load_idx(batch, blockIdx.x * 16, is64);
    if (t < 16) scnt[t] = 0;
#pragma unroll
    for (int i = t; i < 1024; i += 256) sp[i] = 0.f;
    __syncthreads();

    // self-loop term
    uint2 u = hp[(size_t)node * 16 + hl];
    float2 sa = h2f2(u.x);
    float2 sb = h2f2(u.y);

    const int rs = g_rowstart[node];
    const int d  = g_deg[node];
    const int* ep = g_esrc + rs;

    int e = 0;
    for (; e + 8 <= d; e += 8) {
        int s[8];
#pragma unroll
        for (int j = 0; j < 8; j++) s[j] = __ldg(ep + e + j);
        float2 pa0 = make_float2(0.f, 0.f), pa1 = pa0, pa2 = pa0, pa3 = pa0;
        float2 pb0 = pa0, pb1 = pa0, pb2 = pa0, pb3 = pa0;
#pragma unroll
        for (int j = 0; j < 8; j += 4) {
            uint2 v0 = hp[(size_t)s[j + 0] * 16 + hl];
            uint2 v1 = hp[(size_t)s[j + 1] * 16 + hl];
            uint2 v2 = hp[(size_t)s[j + 2] * 16 + hl];
            uint2 v3 = hp[(size_t)s[j + 3] * 16 + hl];
            float2 a0 = h2f2(v0.x), b0 = h2f2(v0.y);
            float2 a1 = h2f2(v1.x), b1 = h2f2(v1.y);
            float2 a2 = h2f2(v2.x), b2 = h2f2(v2.y);
            float2 a3 = h2f2(v3.x), b3 = h2f2(v3.y);
            pa0.x += a0.x; pa0.y += a0.y; pb0.x += b0.x; pb0.y += b0.y;
            pa1.x += a1.x; pa1.y += a1.y; pb1.x += b1.x; pb1.y += b1.y;
            pa2.x += a2.x; pa2.y += a2.y; pb2.x += b2.x; pb2.y += b2.y;
            pa3.x += a3.x; pa3.y += a3.y; pb3.x += b3.x; pb3.y += b3.y;
        }
        sa.x += (pa0.x + pa1.x) + (pa2.x + pa3.x);
        sa.y += (pa0.y + pa1.y) + (pa2.y + pa3.y);
        sb.x += (pb0.x + pb1.x) + (pb2.x + pb3.x);
        sb.y += (pb0.y + pb1.y) + (pb2.y + pb3.y);
    }
    for (; e < d; e++) {
        uint2 v = hp[(size_t)__ldg(ep + e) * 16 + hl];
        float2 a = h2f2(v.x), b = h2f2(v.y);
        sa.x += a.x; sa.y += a.y; sb.x += b.x; sb.y += b.y;
    }

    const float dv = g_dinv[node];
    float4 bb = ((const float4*)bconv)[hl];
    float h0 = fmaxf(fmaf(dv, sa.x, bb.x), 0.f);
    float h1 = fmaxf(fmaf(dv, sa.y, bb.y), 0.f);
    float h2 = fmaxf(fmaf(dv, sb.x, bb.z), 0.f);
    float h3 = fmaxf(fmaf(dv, sb.y, bb.w), 0.f);

    const int g = load_idx(batch, node, is64);
    const int slot = g - sglo;
    if (slot < 16) {
        float* q = sp + slot * 64 + hl * 4;
        atomicAdd(q + 0, h0);
        atomicAdd(q + 1, h1);
        atomicAdd(q + 2, h2);
        atomicAdd(q + 3, h3);
        if (hl == 0) atomicAdd(&scnt[slot], 1);
    } else {
        // degenerate gap fallback (effectively never taken)
        float* pp = g_pool + g * HID + hl * 4;
        asm volatile("red.global.add.v4.f32 [%0], {%1, %2, %3, %4};"
                     :: "l"(pp), "f"(h0), "f"(h1), "f"(h2), "f"(h3) : "memory");
        if (hl == 0) atomicAdd(&g_cnt[g], 1.0f);
    }
    __syncthreads();

    // flush used slots: thread t -> slot t>>4, quad t&15
    const int fs = t >> 4, fq = t & 15;
    const int n = scnt[fs];
    if (n > 0) {
        const int gg = sglo + fs;
        float4 v = *(const float4*)(sp + fs * 64 + fq * 4);
        float* pp = g_pool + gg * HID + fq * 4;
        asm volatile("red.global.add.v4.f32 [%0], {%1, %2, %3, %4};"
                     :: "l"(pp), "f"(v.x), "f"(v.y), "f"(v.z), "f"(v.w) : "memory");
        if (fq == 0) atomicAdd(&g_cnt[gg], (float)n);
    }
}

// ---------------- final: out = (pool/cnt) @ W_lin + b_lin ----------------
__global__ __launch_bounds__(256) void k_final(const float* __restrict__ Wl,
                                               const float* __restrict__ bl,
                                               float* __restrict__ out) {
    __shared__ float sW[HID * OUTC];
    __shared__ float sb[OUTC];
    const int t = threadIdx.x;
    for (int i = t; i < HID * OUTC; i += 256) sW[i] = Wl[i];
    if (t < OUTC) sb[t] = bl[t];
    __syncthreads();

    const float inv = 1.f / fmaxf(g_cnt[t], 1.f);
    float acc[OUTC];
#pragma unroll
    for (int j = 0; j < OUTC; j++) acc[j] = sb[j];
#pragma unroll 4
    for (int c = 0; c < HID; c++) {
        float p = g_pool[t * HID + c] * inv;
#pragma unroll
        for (int j = 0; j < OUTC; j++) acc[j] = fmaf(p, sW[c * OUTC + j], acc[j]);
    }
#pragma unroll
    for (int j = 0; j < OUTC; j++) out[t * OUTC + j] = acc[j];
}

// ---------------- launch ----------------
extern "C" void kernel_launch(void* const* d_in, const int* in_sizes, int n_in,
                              void* d_out, int out_size) {
    const float* x     = (const float*)d_in[0];
    const void*  ei    = d_in[1];
    const void*  batch = d_in[2];
    const float* Wc    = (const float*)d_in[3];
    const float* bc    = (const float*)d_in[4];
    const float* Wl    = (const float*)d_in[5];
    const float* bl    = (const float*)d_in[6];
    float*       out   = (float*)d_out;

    k_setup     <<<(N_NODES + 255) / 256, 256>>>((const unsigned*)ei);
    k_degcount  <<<(N_EDGES + 255) / 256, 256>>>(ei);
    k_scanfused <<<SCAN_NB, SCAN_B>>>();
    k_gemm      <<<(N_NODES + 127) / 128, 256>>>(x, Wc);   // index 3: profiled
    k_fill      <<<(N_EDGES + 255) / 256, 256>>>(ei);
    k_agg       <<<(N_NODES / 2 * 32) / 256, 256>>>(batch, bc);
    k_final     <<<1, 256>>>(Wl, bl, out);
}

// round 11
// speedup vs baseline: 4.1784x; 1.0397x over previous
#include <cuda_runtime.h>
#include <cuda_fp16.h>
#include <cstdint>

#define N_NODES 100000
#define N_EDGES 1600000
#define IN_CH   128
#define HID     64
#define NG      256
#define OUTC    10

#define SCAN_B  1024
#define SCAN_NB ((N_NODES + SCAN_B - 1) / SCAN_B)   // 98

#define GEMM_SMEM (2 * 128 * 36 * 4 + 128 * 72 * 4)  // 73728 B

typedef unsigned long long u64;

// ---------------- scratch (device globals; no allocation) ----------------
__device__ int    g_is64;
__device__ __align__(16) int    g_deg[N_NODES];
__device__ __align__(16) int    g_rowstart[N_NODES];
__device__ __align__(16) int    g_cursor[N_NODES];
__device__ __align__(16) int    g_esrc[N_EDGES];     // CSR: src per edge, bucketed by dst
__device__ __align__(16) int    g_bsum[SCAN_NB];
__device__ volatile int         g_sflag[SCAN_NB];
__device__ __align__(16) float  g_dinv[N_NODES];
__device__ __align__(16) __half g_hs [(size_t)N_NODES * HID];  // (x@W)*dinv, fp16
__device__ __align__(16) float  g_pool[NG * HID];
__device__ __align__(16) float  g_cnt [NG];

// index loader handling int64-vs-int32 edge/batch buffers
__device__ __forceinline__ int load_idx(const void* p, long long i, int is64) {
    if (is64) return (int)((const long long*)p)[i];
    return ((const int*)p)[i];
}

__device__ __forceinline__ unsigned h2_bits(__half2 h) {
    return *reinterpret_cast<unsigned*>(&h);
}
__device__ __forceinline__ float2 h2f2(unsigned b) {
    __half2 h = *reinterpret_cast<__half2*>(&b);
    return __half22float2(h);
}
__device__ __forceinline__ void cp16(unsigned dst, const void* src) {
    asm volatile("cp.async.cg.shared.global [%0], [%1], 16;" :: "r"(dst), "l"(src));
}

// ---------------- setup: zero counters/flags + parallel dtype sniff ----------
__global__ void k_setup(const unsigned* __restrict__ e) {
    int i = blockIdx.x * blockDim.x + threadIdx.x;
    if (i < N_NODES) g_deg[i] = 0;
    if (i < NG * HID) g_pool[i] = 0.f;
    if (i < NG) g_cnt[i] = 0.f;
    if (i < SCAN_NB) g_sflag[i] = 0;
    if (blockIdx.x == 0 && threadIdx.x < 32) {
        unsigned nz = e[2 * threadIdx.x + 1] | e[2 * (threadIdx.x + 32) + 1];
        unsigned any = __ballot_sync(0xffffffffu, nz != 0u);
        if (threadIdx.x == 0) g_is64 = (any == 0u);
    }
}

// ---------------- in-degree count over dst (edges only) ----------------
__global__ void k_degcount(const void* __restrict__ ei) {
    int i = blockIdx.x * blockDim.x + threadIdx.x;
    if (i < N_EDGES) {
        int d = load_idx(ei, (long long)N_EDGES + i, g_is64);
        atomicAdd(&g_deg[d], 1);
    }
}

// ---------------- fused scan: block scan + decoupled lookback + emit ---------
__global__ __launch_bounds__(SCAN_B) void k_scanfused() {
    __shared__ int ws[32];
    __shared__ int s_off;
    const int b = blockIdx.x;
    const int t = threadIdx.x;
    const int lane = t & 31, wid = t >> 5;
    const int i = b * SCAN_B + t;
    int d = (i < N_NODES) ? g_deg[i] : 0;
    int v = d;
#pragma unroll
    for (int o = 1; o < 32; o <<= 1) {
        int u = __shfl_up_sync(0xffffffffu, v, o);
        if (lane >= o) v += u;
    }
    if (lane == 31) ws[wid] = v;
    __syncthreads();
    if (t < 32) {
        int w = ws[t];
#pragma unroll
        for (int o = 1; o < 32; o <<= 1) {
            int u = __shfl_up_sync(0xffffffffu, w, o);
            if (t >= o) w += u;
        }
        ws[t] = w;
    }
    __syncthreads();
    if (t == 0) {
        g_bsum[b] = ws[31];
        __threadfence();
        g_sflag[b] = 1;
    }
    if (t < 32) {
        int off = 0;
        for (int base = 0; base < b; base += 32) {
            int idx = base + lane;
            bool need = (idx < b);
            while (__ballot_sync(0xffffffffu, need && (g_sflag[idx] == 0))) { }
            if (need) off += *(volatile int*)&g_bsum[idx];
        }
#pragma unroll
        for (int o = 16; o > 0; o >>= 1) off += __shfl_down_sync(0xffffffffu, off, o);
        if (lane == 0) s_off = off;
    }
    __syncthreads();
    int ex = (v - d) + (wid ? ws[wid - 1] : 0) + s_off;
    if (i < N_NODES) {
        g_rowstart[i] = ex;
        g_cursor[i]   = ex;
        g_dinv[i]     = rsqrtf((float)(d + 1));    // +1 self loop
    }
}

// ---------------- GEMM: hs = (x @ W) * dinv -----------------------------------
// tf32 tensor cores on RAW fp32 bits (HW ignores low mantissa; no cvt at all).
// cp.async double-buffered X (2x18KB) + whole W resident (36KB), 72KB dyn smem.
// block tile 128x64, 8 warps 4x2, warp tile 32x32; K=128 in 4 pipelined phases.
__global__ __launch_bounds__(256) void k_gemm(const float* __restrict__ x,
                                              const float* __restrict__ W) {
    extern __shared__ __align__(16) float smem[];
    float* Xs  = smem;                    // 2 buffers of 128*36
    float* Wsm = smem + 2 * 128 * 36;     // 128*72

    const int t      = threadIdx.x;
    const int wid    = t >> 5;
    const int lane   = t & 31;
    const int warp_m = wid & 3;
    const int warp_n = wid >> 2;
    const int g      = lane >> 2;
    const int tig    = lane & 3;
    const int row0   = blockIdx.x * 128;

    const unsigned sX0 = (unsigned)__cvta_generic_to_shared(Xs);
    const unsigned sX1 = (unsigned)__cvta_generic_to_shared(Xs + 128 * 36);
    const unsigned sW  = (unsigned)__cvta_generic_to_shared(Wsm);

    // group 0: whole W (128x64 = 2048 float4) + X phase 0 (1024 float4)
#pragma unroll
    for (int i = t; i < 2048; i += 256) {
        int kk = i >> 4, n4 = i & 15;
        cp16(sW + (unsigned)(kk * 72 + n4 * 4) * 4u, W + (size_t)kk * HID + n4 * 4);
    }
#pragma unroll
    for (int i = t; i < 1024; i += 256) {
        int rr = i >> 3, k4 = i & 7;
        int gr = row0 + rr;
        if (gr >= N_NODES) gr = N_NODES - 1;
        cp16(sX0 + (unsigned)(rr * 36 + k4 * 4) * 4u, x + (size_t)gr * IN_CH + k4 * 4);
    }
    asm volatile("cp.async.commit_group;");

    float c[2][4][4];
#pragma unroll
    for (int mt = 0; mt < 2; mt++)
#pragma unroll
        for (int nt = 0; nt < 4; nt++)
#pragma unroll
            for (int j = 0; j < 4; j++) c[mt][nt][j] = 0.f;

    const unsigned bufs[2] = { sX0, sX1 };

    for (int ph = 0; ph < 4; ph++) {
        if (ph < 3) {
            const unsigned dst = bufs[(ph + 1) & 1];
#pragma unroll
            for (int i = t; i < 1024; i += 256) {
                int rr = i >> 3, k4 = i & 7;
                int gr = row0 + rr;
                if (gr >= N_NODES) gr = N_NODES - 1;
                cp16(dst + (unsigned)(rr * 36 + k4 * 4) * 4u,
                     x + (size_t)gr * IN_CH + (ph + 1) * 32 + k4 * 4);
            }
            asm volatile("cp.async.commit_group;");
            asm volatile("cp.async.wait_group 1;");
        } else {
            asm volatile("cp.async.wait_group 0;");
        }
        __syncthreads();

        const unsigned* Xu = (const unsigned*)(Xs + (ph & 1) * 128 * 36);
        const unsigned* Wu = (const unsigned*)Wsm;

#pragma unroll
        for (int ks = 0; ks < 4; ks++) {
            const int k_off = ks * 8;
            unsigned a[2][4], bfr[4][2];
#pragma unroll
            for (int mt = 0; mt < 2; mt++) {
                int br = warp_m * 32 + mt * 16 + g;
                a[mt][0] = Xu[br * 36 + k_off + tig];
                a[mt][1] = Xu[(br + 8) * 36 + k_off + tig];
                a[mt][2] = Xu[br * 36 + k_off + tig + 4];
                a[mt][3] = Xu[(br + 8) * 36 + k_off + tig + 4];
            }
            const int krow = ph * 32 + k_off + tig;
#pragma unroll
            for (int nt = 0; nt < 4; nt++) {
                int n_off = warp_n * 32 + nt * 8 + g;
                bfr[nt][0] = Wu[krow * 72 + n_off];
                bfr[nt][1] = Wu[(krow + 4) * 72 + n_off];
            }
#pragma unroll
            for (int mt = 0; mt < 2; mt++)
#pragma unroll
                for (int nt = 0; nt < 4; nt++) {
                    asm("mma.sync.aligned.m16n8k8.row.col.f32.tf32.tf32.f32 "
                        "{%0,%1,%2,%3}, {%4,%5,%6,%7}, {%8,%9}, {%0,%1,%2,%3};"
                        : "+f"(c[mt][nt][0]), "+f"(c[mt][nt][1]),
                          "+f"(c[mt][nt][2]), "+f"(c[mt][nt][3])
                        : "r"(a[mt][0]), "r"(a[mt][1]), "r"(a[mt][2]), "r"(a[mt][3]),
                          "r"(bfr[nt][0]), "r"(bfr[nt][1]));
                }
        }
        __syncthreads();
    }

    // epilogue: scale by dinv, pack fp16, store
#pragma unroll
    for (int mt = 0; mt < 2; mt++) {
        int r0 = row0 + warp_m * 32 + mt * 16 + g;
        int r1 = r0 + 8;
        float dv0 = (r0 < N_NODES) ? g_dinv[r0] : 0.f;
        float dv1 = (r1 < N_NODES) ? g_dinv[r1] : 0.f;
#pragma unroll
        for (int nt = 0; nt < 4; nt++) {
            int col = warp_n * 32 + nt * 8 + tig * 2;
            if (r0 < N_NODES) {
                __half2 h = __floats2half2_rn(c[mt][nt][0] * dv0, c[mt][nt][1] * dv0);
                *(unsigned*)(g_hs + (size_t)r0 * HID + col) = h2_bits(h);
            }
            if (r1 < N_NODES) {
                __half2 h = __floats2half2_rn(c[mt][nt][2] * dv1, c[mt][nt][3] * dv1);
                *(unsigned*)(g_hs + (size_t)r1 * HID + col) = h2_bits(h);
            }
        }
    }
}

// ---------------- CSR fill: bucket src by dst ----------------
__global__ void k_fill(const void* __restrict__ ei) {
    int i = blockIdx.x * blockDim.x + threadIdx.x;
    if (i < N_EDGES) {
        const int is64 = g_is64;
        int s = load_idx(ei, i, is64);
        int d = load_idx(ei, (long long)N_EDGES + i, is64);
        int pos = atomicAdd(&g_cursor[d], 1);
        g_esrc[pos] = s;
    }
}

// ---------------- aggregate + relu + smem-pooled reduction ----------------
// Block = 16 consecutive nodes (8 warps x 2). batch is sorted, so the block's
// graph ids span a tiny range: accumulate in a 16-slot smem pool, flush only
// used slots (cuts global red.v4 count ~10x).
__global__ __launch_bounds__(256) void k_agg(const void* __restrict__ batch,
                                             const float* __restrict__ bconv) {
    __shared__ __align__(16) float sp[16 * 64];   // slot-major pool accum
    __shared__ int scnt[16];
    __shared__ int sglo;

    const int t    = threadIdx.x;
    const int gt   = blockIdx.x * 256 + t;
    const int warp = gt >> 5;
    const int lane = gt & 31;
    const int node = warp * 2 + (lane >> 4);
    const int hl   = lane & 15;
    const int is64 = g_is64;
    const uint2* hp = (const uint2*)g_hs;    // row = 16 uint2 (128B)

    // init smem
    if (t == 0) sglo = load_idx(batch, blockIdx.x * 16, is64);
    if (t < 16) scnt[t] = 0;
#pragma unroll
    for (int i = t; i < 1024; i += 256) sp[i] = 0.f;
    __syncthreads();

    // self-loop term
    uint2 u = hp[(size_t)node * 16 + hl];
    float2 sa = h2f2(u.x);
    float2 sb = h2f2(u.y);

    const int rs = g_rowstart[node];
    const int d  = g_deg[node];
    const int* ep = g_esrc + rs;

    int e = 0;
    for (; e + 8 <= d; e += 8) {
        int s[8];
#pragma unroll
        for (int j = 0; j < 8; j++) s[j] = __ldg(ep + e + j);
        float2 pa0 = make_float2(0.f, 0.f), pa1 = pa0, pa2 = pa0, pa3 = pa0;
        float2 pb0 = pa0, pb1 = pa0, pb2 = pa0, pb3 = pa0;
#pragma unroll
        for (int j = 0; j < 8; j += 4) {
            uint2 v0 = hp[(size_t)s[j + 0] * 16 + hl];
            uint2 v1 = hp[(size_t)s[j + 1] * 16 + hl];
            uint2 v2 = hp[(size_t)s[j + 2] * 16 + hl];
            uint2 v3 = hp[(size_t)s[j + 3] * 16 + hl];
            float2 a0 = h2f2(v0.x), b0 = h2f2(v0.y);
            float2 a1 = h2f2(v1.x), b1 = h2f2(v1.y);
            float2 a2 = h2f2(v2.x), b2 = h2f2(v2.y);
            float2 a3 = h2f2(v3.x), b3 = h2f2(v3.y);
            pa0.x += a0.x; pa0.y += a0.y; pb0.x += b0.x; pb0.y += b0.y;
            pa1.x += a1.x; pa1.y += a1.y; pb1.x += b1.x; pb1.y += b1.y;
            pa2.x += a2.x; pa2.y += a2.y; pb2.x += b2.x; pb2.y += b2.y;
            pa3.x += a3.x; pa3.y += a3.y; pb3.x += b3.x; pb3.y += b3.y;
        }
        sa.x += (pa0.x + pa1.x) + (pa2.x + pa3.x);
        sa.y += (pa0.y + pa1.y) + (pa2.y + pa3.y);
        sb.x += (pb0.x + pb1.x) + (pb2.x + pb3.x);
        sb.y += (pb0.y + pb1.y) + (pb2.y + pb3.y);
    }
    for (; e < d; e++) {
        uint2 v = hp[(size_t)__ldg(ep + e) * 16 + hl];
        float2 a = h2f2(v.x), b = h2f2(v.y);
        sa.x += a.x; sa.y += a.y; sb.x += b.x; sb.y += b.y;
    }

    const float dv = g_dinv[node];
    float4 bb = ((const float4*)bconv)[hl];
    float h0 = fmaxf(fmaf(dv, sa.x, bb.x), 0.f);
    float h1 = fmaxf(fmaf(dv, sa.y, bb.y), 0.f);
    float h2 = fmaxf(fmaf(dv, sb.x, bb.z), 0.f);
    float h3 = fmaxf(fmaf(dv, sb.y, bb.w), 0.f);

    const int g = load_idx(batch, node, is64);
    const int slot = g - sglo;
    if (slot < 16) {
        float* q = sp + slot * 64 + hl * 4;
        atomicAdd(q + 0, h0);
        atomicAdd(q + 1, h1);
        atomicAdd(q + 2, h2);
        atomicAdd(q + 3, h3);
        if (hl == 0) atomicAdd(&scnt[slot], 1);
    } else {
        // degenerate gap fallback (effectively never taken)
        float* pp = g_pool + g * HID + hl * 4;
        asm volatile("red.global.add.v4.f32 [%0], {%1, %2, %3, %4};"
                     :: "l"(pp), "f"(h0), "f"(h1), "f"(h2), "f"(h3) : "memory");
        if (hl == 0) atomicAdd(&g_cnt[g], 1.0f);
    }
    __syncthreads();

    // flush used slots: thread t -> slot t>>4, quad t&15
    const int fs = t >> 4, fq = t & 15;
    const int n = scnt[fs];
    if (n > 0) {
        const int gg = sglo + fs;
        float4 v = *(const float4*)(sp + fs * 64 + fq * 4);
        float* pp = g_pool + gg * HID + fq * 4;
        asm volatile("red.global.add.v4.f32 [%0], {%1, %2, %3, %4};"
                     :: "l"(pp), "f"(v.x), "f"(v.y), "f"(v.z), "f"(v.w) : "memory");
        if (fq == 0) atomicAdd(&g_cnt[gg], (float)n);
    }
}

// ---------------- final: out = (pool/cnt) @ W_lin + b_lin ----------------
__global__ __launch_bounds__(256) void k_final(const float* __restrict__ Wl,
                                               const float* __restrict__ bl,
                                               float* __restrict__ out) {
    __shared__ float sW[HID * OUTC];
    __shared__ float sb[OUTC];
    const int t = threadIdx.x;
    for (int i = t; i < HID * OUTC; i += 256) sW[i] = Wl[i];
    if (t < OUTC) sb[t] = bl[t];
    __syncthreads();

    const float inv = 1.f / fmaxf(g_cnt[t], 1.f);
    float acc[OUTC];
#pragma unroll
    for (int j = 0; j < OUTC; j++) acc[j] = sb[j];
#pragma unroll 4
    for (int c = 0; c < HID; c++) {
        float p = g_pool[t * HID + c] * inv;
#pragma unroll
        for (int j = 0; j < OUTC; j++) acc[j] = fmaf(p, sW[c * OUTC + j], acc[j]);
    }
#pragma unroll
    for (int j = 0; j < OUTC; j++) out[t * OUTC + j] = acc[j];
}

// ---------------- launch ----------------
extern "C" void kernel_launch(void* const* d_in, const int* in_sizes, int n_in,
                              void* d_out, int out_size) {
    const float* x     = (const float*)d_in[0];
    const void*  ei    = d_in[1];
    const void*  batch = d_in[2];
    const float* Wc    = (const float*)d_in[3];
    const float* bc    = (const float*)d_in[4];
    const float* Wl    = (const float*)d_in[5];
    const float* bl    = (const float*)d_in[6];
    float*       out   = (float*)d_out;

    cudaFuncSetAttribute(k_gemm, cudaFuncAttributeMaxDynamicSharedMemorySize, GEMM_SMEM);

    k_setup     <<<(N_NODES + 255) / 256, 256>>>((const unsigned*)ei);
    k_degcount  <<<(N_EDGES + 255) / 256, 256>>>(ei);
    k_scanfused <<<SCAN_NB, SCAN_B>>>();
    k_gemm      <<<(N_NODES + 127) / 128, 256, GEMM_SMEM>>>(x, Wc);   // index 3: profiled
    k_fill      <<<(N_EDGES + 255) / 256, 256>>>(ei);
    k_agg       <<<(N_NODES / 2 * 32) / 256, 256>>>(batch, bc);
    k_final     <<<1, 256>>>(Wl, bl, out);
}